// round 2
// baseline (speedup 1.0000x reference)
#include <cuda_runtime.h>

#define BB 16
#define NN 4096
#define SS 1024
#define NQ (BB*SS)        /* 16384 queries */
#define KMAX 64
#define CIN 67
#define CF  64

/* ---------------- scratch (device globals; no allocation allowed) -------- */
__device__ int    g_knn[NQ*KMAX];
__device__ float  g_newxyz[NQ*3];
__device__ float  g_buf1[(size_t)NQ*KMAX*64];
__device__ float  g_buf2[(size_t)NQ*KMAX*64];
__device__ float  g_buf3[(size_t)NQ*KMAX*128];
__device__ double g_sum[128];
__device__ double g_sq[128];
__device__ float  g_scl[128];
__device__ float  g_shf[128];

/* ------------------------------- FPS ------------------------------------ */
__global__ void __launch_bounds__(1024) fps_kernel(const float* __restrict__ xyz,
                                                   float* __restrict__ out_newxyz)
{
    const int b = blockIdx.x;
    const int t = threadIdx.x;
    const int lane = t & 31, wid = t >> 5;
    const float* X = xyz + (size_t)b*NN*3;

    float px[4], py[4], pz[4], dd[4];
#pragma unroll
    for (int j = 0; j < 4; j++) {
        int p = t + 1024*j;
        px[j] = X[p*3+0]; py[j] = X[p*3+1]; pz[j] = X[p*3+2];
        dd[j] = 1e10f;
    }
    __shared__ unsigned long long wb[32];
    int far = 0;

    for (int it = 0; it < SS; ++it) {
        float cx = X[far*3+0], cy = X[far*3+1], cz = X[far*3+2];
        if (t == 0) {
            int o = b*SS + it;
            out_newxyz[o*3+0] = cx; out_newxyz[o*3+1] = cy; out_newxyz[o*3+2] = cz;
            g_newxyz[o*3+0]  = cx; g_newxyz[o*3+1]  = cy; g_newxyz[o*3+2]  = cz;
        }
        unsigned long long best = 0ull;
#pragma unroll
        for (int j = 0; j < 4; j++) {
            float dx = px[j]-cx, dy = py[j]-cy, dz = pz[j]-cz;
            float d  = fmaf(dz, dz, fmaf(dy, dy, dx*dx));
            dd[j] = fminf(dd[j], d);
            int p = t + 1024*j;
            unsigned long long key =
                (((unsigned long long)__float_as_uint(dd[j])) << 32) | (unsigned)(NN-1-p);
            best = (key > best) ? key : best;
        }
#pragma unroll
        for (int o = 16; o; o >>= 1) {
            unsigned long long v = __shfl_xor_sync(0xffffffffu, best, o);
            if (v > best) best = v;
        }
        if (lane == 0) wb[wid] = best;
        __syncthreads();
        unsigned long long v = wb[lane];
#pragma unroll
        for (int o = 16; o; o >>= 1) {
            unsigned long long u = __shfl_xor_sync(0xffffffffu, v, o);
            if (u > v) v = u;
        }
        far = NN - 1 - (int)(v & 0xffffffffu);
        __syncthreads();
    }
}

/* ------------------------------- kNN ------------------------------------ */
__device__ __forceinline__ unsigned mono_f32(float v)
{
    unsigned u = __float_as_uint(v);
    return (u & 0x80000000u) ? ~u : (u | 0x80000000u);
}

__global__ void __launch_bounds__(128) knn_kernel(const float* __restrict__ xyz)
{
    const int q = blockIdx.x;
    const int b = q >> 10;
    const int t = threadIdx.x;
    __shared__ float d2s[NN];
    __shared__ unsigned long long lmin[128];
    __shared__ unsigned long long bestsh;
    const float* X = xyz + (size_t)b*NN*3;

    float qx = g_newxyz[q*3+0], qy = g_newxyz[q*3+1], qz = g_newxyz[q*3+2];
    float qq = qx*qx + qy*qy + qz*qz;

    for (int p = t; p < NN; p += 128) {
        float x = X[p*3+0], y = X[p*3+1], z = X[p*3+2];
        float pp  = x*x + y*y + z*z;
        float dot = qx*x + qy*y + qz*z;
        d2s[p] = qq + pp - 2.0f*dot;       /* same formula as reference sq_cdist */
    }
    __syncthreads();

    unsigned long long k = 0xffffffffffffffffull;
#pragma unroll 8
    for (int i = 0; i < 32; i++) {
        int p = t + 128*i;
        unsigned long long kk = (((unsigned long long)mono_f32(d2s[p])) << 32) | (unsigned)p;
        if (kk < k) k = kk;
    }
    lmin[t] = k;

    for (int r = 0; r < KMAX; r++) {
        __syncthreads();
        if (t < 32) {
            unsigned long long v = lmin[t];
            unsigned long long a = lmin[t+32]; if (a < v) v = a;
            a = lmin[t+64]; if (a < v) v = a;
            a = lmin[t+96]; if (a < v) v = a;
#pragma unroll
            for (int o = 16; o; o >>= 1) {
                unsigned long long u = __shfl_xor_sync(0xffffffffu, v, o);
                if (u < v) v = u;
            }
            if (t == 0) bestsh = v;
        }
        __syncthreads();
        unsigned long long w = bestsh;
        int p = (int)(w & 0xffffffffu);
        if (t == 0) g_knn[q*KMAX + r] = p;
        if ((p & 127) == t) {                 /* owner: invalidate + rescan */
            d2s[p] = __int_as_float(0x7f800000);
            unsigned long long nk = 0xffffffffffffffffull;
#pragma unroll 8
            for (int i = 0; i < 32; i++) {
                int pp2 = t + 128*i;
                unsigned long long kk =
                    (((unsigned long long)mono_f32(d2s[pp2])) << 32) | (unsigned)pp2;
                if (kk < nk) nk = kk;
            }
            lmin[t] = nk;
        }
    }
}

/* -------------------- conv1: gather + concat + 67->64 GEMM -------------- */
__global__ void __launch_bounds__(256) conv1_kernel(const float* __restrict__ xyz,
                                                    const float* __restrict__ feat,
                                                    const float* __restrict__ W, /* [64][67] */
                                                    int lgk)
{
    __shared__ float Xs[CIN][64];
    __shared__ float Ws[CIN][64];
    __shared__ float ssum[64], ssq[64];
    const int t = threadIdx.x;
    const int tile = blockIdx.x;

    if (t < 64) { ssum[t] = 0.f; ssq[t] = 0.f; }

    for (int i = t; i < CIN*64; i += 256) {
        int in = i >> 6, o = i & 63;
        Ws[in][o] = W[o*CIN + in];
    }
    {
        const int lr = t >> 2, sub = t & 3;
        const int gr = tile*64 + lr;
        const int q  = gr >> lgk;
        const int j  = gr & ((1 << lgk) - 1);
        const int n  = g_knn[q*KMAX + j];
        const int b  = q >> 10;
        const float* fp = feat + ((size_t)(b*NN + n))*CF;
#pragma unroll
        for (int t4 = 0; t4 < 4; t4++) {
            int fi = sub*4 + t4;
            float4 v = *(const float4*)(fp + fi*4);
            Xs[3+fi*4+0][lr] = v.x; Xs[3+fi*4+1][lr] = v.y;
            Xs[3+fi*4+2][lr] = v.z; Xs[3+fi*4+3][lr] = v.w;
        }
        if (sub == 0) {
            const float* xp = xyz + (size_t)(b*NN + n)*3;
            Xs[0][lr] = xp[0] - g_newxyz[q*3+0];
            Xs[1][lr] = xp[1] - g_newxyz[q*3+1];
            Xs[2][lr] = xp[2] - g_newxyz[q*3+2];
        }
    }
    __syncthreads();

    const int rg = t & 15, cg = t >> 4;
    float acc[4][4];
#pragma unroll
    for (int r = 0; r < 4; r++)
#pragma unroll
        for (int c = 0; c < 4; c++) acc[r][c] = 0.f;

    for (int kk = 0; kk < CIN; kk++) {
        float4 a  = *(const float4*)&Xs[kk][rg*4];
        float4 wv = *(const float4*)&Ws[kk][cg*4];
        float av[4] = {a.x, a.y, a.z, a.w};
        float bv[4] = {wv.x, wv.y, wv.z, wv.w};
#pragma unroll
        for (int r = 0; r < 4; r++)
#pragma unroll
            for (int c = 0; c < 4; c++)
                acc[r][c] = fmaf(av[r], bv[c], acc[r][c]);
    }

    const int gr0 = tile*64 + rg*4;
#pragma unroll
    for (int r = 0; r < 4; r++) {
        float4 o = make_float4(acc[r][0], acc[r][1], acc[r][2], acc[r][3]);
        *(float4*)&g_buf1[(size_t)(gr0+r)*64 + cg*4] = o;
    }
#pragma unroll
    for (int c = 0; c < 4; c++) {
        float s  = acc[0][c] + acc[1][c] + acc[2][c] + acc[3][c];
        float sq = acc[0][c]*acc[0][c] + acc[1][c]*acc[1][c]
                 + acc[2][c]*acc[2][c] + acc[3][c]*acc[3][c];
        atomicAdd(&ssum[cg*4+c], s);
        atomicAdd(&ssq[cg*4+c], sq);
    }
    __syncthreads();
    if (t < 64) {
        atomicAdd(&g_sum[t], (double)ssum[t]);
        atomicAdd(&g_sq[t],  (double)ssq[t]);
    }
}

/* -------- convN: BN+ReLU(load) + 64->COLS GEMM, LAYER=2 or 3 ------------ */
template<int LAYER>
__global__ void __launch_bounds__(256) convN_kernel(const float* __restrict__ W /* [colsTot][64] */)
{
    const float* bufIn  = (LAYER == 2) ? g_buf1 : g_buf2;
    float*       bufOut = (LAYER == 2) ? g_buf2 : g_buf3;
    const int colsTot   = (LAYER == 2) ? 64 : 128;

    __shared__ float Xs[64][64];
    __shared__ float Ws[64][64];
    __shared__ float sc[64], sh[64], ssum[64], ssq[64];
    const int t = threadIdx.x;
    const int tile   = blockIdx.x;
    const int colOff = blockIdx.y * 64;

    if (t < 64) { sc[t] = g_scl[t]; sh[t] = g_shf[t]; ssum[t] = 0.f; ssq[t] = 0.f; }
    __syncthreads();

    for (int i = t; i < 64*64; i += 256) {
        int in = i >> 6, o = i & 63;
        Ws[in][o] = W[(size_t)(colOff + o)*64 + in];
    }
    {
        const int lr = t >> 2, sub = t & 3;
        const size_t gr = (size_t)tile*64 + lr;
        const float* ip = bufIn + gr*64;
#pragma unroll
        for (int t4 = 0; t4 < 4; t4++) {
            int fi = sub*4 + t4;
            float4 v = *(const float4*)(ip + fi*4);
            int c0 = fi*4;
            Xs[c0+0][lr] = fmaxf(fmaf(v.x, sc[c0+0], sh[c0+0]), 0.f);
            Xs[c0+1][lr] = fmaxf(fmaf(v.y, sc[c0+1], sh[c0+1]), 0.f);
            Xs[c0+2][lr] = fmaxf(fmaf(v.z, sc[c0+2], sh[c0+2]), 0.f);
            Xs[c0+3][lr] = fmaxf(fmaf(v.w, sc[c0+3], sh[c0+3]), 0.f);
        }
    }
    __syncthreads();

    const int rg = t & 15, cg = t >> 4;
    float acc[4][4];
#pragma unroll
    for (int r = 0; r < 4; r++)
#pragma unroll
        for (int c = 0; c < 4; c++) acc[r][c] = 0.f;

#pragma unroll 4
    for (int kk = 0; kk < 64; kk++) {
        float4 a  = *(const float4*)&Xs[kk][rg*4];
        float4 wv = *(const float4*)&Ws[kk][cg*4];
        float av[4] = {a.x, a.y, a.z, a.w};
        float bv[4] = {wv.x, wv.y, wv.z, wv.w};
#pragma unroll
        for (int r = 0; r < 4; r++)
#pragma unroll
            for (int c = 0; c < 4; c++)
                acc[r][c] = fmaf(av[r], bv[c], acc[r][c]);
    }

    const size_t gr0 = (size_t)tile*64 + (size_t)rg*4;
#pragma unroll
    for (int r = 0; r < 4; r++) {
        float4 o = make_float4(acc[r][0], acc[r][1], acc[r][2], acc[r][3]);
        *(float4*)&bufOut[(gr0+r)*colsTot + colOff + cg*4] = o;
    }
#pragma unroll
    for (int c = 0; c < 4; c++) {
        float s  = acc[0][c] + acc[1][c] + acc[2][c] + acc[3][c];
        float sq = acc[0][c]*acc[0][c] + acc[1][c]*acc[1][c]
                 + acc[2][c]*acc[2][c] + acc[3][c]*acc[3][c];
        atomicAdd(&ssum[cg*4+c], s);
        atomicAdd(&ssq[cg*4+c], sq);
    }
    __syncthreads();
    if (t < 64) {
        atomicAdd(&g_sum[colOff + t], (double)ssum[t]);
        atomicAdd(&g_sq[colOff + t],  (double)ssq[t]);
    }
}

/* -------------- stats: sums -> (scale, shift); re-zero accumulators ------ */
__global__ void stats_kernel(const float* __restrict__ gamma,
                             const float* __restrict__ beta,
                             int C, double invn)
{
    int c = threadIdx.x;
    if (c < C) {
        double s = g_sum[c], q = g_sq[c];
        double mu = s * invn;
        double var = q * invn - mu * mu;
        float rstd = rsqrtf((float)var + 1e-5f);
        float scl = gamma[c] * rstd;
        g_scl[c] = scl;
        g_shf[c] = beta[c] - (float)mu * scl;
        g_sum[c] = 0.0;
        g_sq[c]  = 0.0;
    }
}

/* -------- finalize: BN + ReLU + max over neighbors -> out ---------------- */
__global__ void __launch_bounds__(128) finalize_kernel(float* __restrict__ out, int k, int base)
{
    const int q = blockIdx.x;
    const int c = threadIdx.x;
    const float scl = g_scl[c], shf = g_shf[c];
    float m = 0.f;                        /* relu => max(0, max_j pre-relu)  */
    const float* p = g_buf3 + (size_t)q*k*128 + c;
    for (int j = 0; j < k; j++) {
        float v = fmaf(p[(size_t)j*128], scl, shf);
        m = fmaxf(m, v);
    }
    out[(size_t)NQ*3 + (size_t)q*384 + base + c] = m;
}

/* ------------------------------ driver ----------------------------------- */
extern "C" void kernel_launch(void* const* d_in, const int* in_sizes, int n_in,
                              void* d_out, int out_size)
{
    const float* xyz  = (const float*)d_in[0];
    const float* feat = (const float*)d_in[1];
    const float* w0   = (const float*)d_in[2];
    const float* w1   = (const float*)d_in[3];
    const float* w2   = (const float*)d_in[4];
    const float* g0   = (const float*)d_in[5];
    const float* g1   = (const float*)d_in[6];
    const float* g2   = (const float*)d_in[7];
    const float* b0   = (const float*)d_in[8];
    const float* b1   = (const float*)d_in[9];
    const float* b2   = (const float*)d_in[10];
    float* out = (float*)d_out;

    fps_kernel<<<BB, 1024>>>(xyz, out);
    knn_kernel<<<NQ, 128>>>(xyz);

    const int KS[3]  = {16, 32, 64};
    const int LGK[3] = {4, 5, 6};
    for (int s = 0; s < 3; s++) {
        const int k = KS[s];
        const int R = NQ * k;
        const double invn = 1.0 / (double)R;

        conv1_kernel<<<R/64, 256>>>(xyz, feat, w0 + (size_t)s*64*CIN, LGK[s]);
        stats_kernel<<<1, 128>>>(g0 + s*64, b0 + s*64, 64, invn);

        convN_kernel<2><<<dim3(R/64, 1), 256>>>(w1 + (size_t)s*64*64);
        stats_kernel<<<1, 128>>>(g1 + s*64, b1 + s*64, 64, invn);

        convN_kernel<3><<<dim3(R/64, 2), 256>>>(w2 + (size_t)s*128*64);
        stats_kernel<<<1, 128>>>(g2 + s*128, b2 + s*128, 128, invn);

        finalize_kernel<<<NQ, 128>>>(out, k, s*128);
    }
}

// round 3
// speedup vs baseline: 1.2717x; 1.2717x over previous
#include <cuda_runtime.h>

#define BB 16
#define NN 4096
#define SS 1024
#define NQ (BB*SS)        /* 16384 queries */
#define KMAX 64
#define CIN 67
#define CF  64

/* ---------------- scratch (device globals; no allocation allowed) -------- */
__device__ int    g_knn[NQ*KMAX];
__device__ float  g_newxyz[NQ*3];
__device__ float  g_buf1[(size_t)NQ*KMAX*64];
__device__ float  g_buf2[(size_t)NQ*KMAX*64];
__device__ float  g_max[NQ*128];
__device__ float  g_min[NQ*128];
__device__ double g_sum[128];
__device__ double g_sq[128];
__device__ float  g_scl[128];
__device__ float  g_shf[128];

/* ---------------- packed f32x2 helpers (FFMA2 = full-rate fp32) ---------- */
__device__ __forceinline__ unsigned long long dup2f(float v)
{
    unsigned long long r;
    asm("mov.b64 %0, {%1, %1};" : "=l"(r) : "f"(v));
    return r;
}
__device__ __forceinline__ unsigned long long ffma2(unsigned long long a,
                                                    unsigned long long b,
                                                    unsigned long long c)
{
    unsigned long long d;
    asm("fma.rn.f32x2 %0, %1, %2, %3;" : "=l"(d) : "l"(a), "l"(b), "l"(c));
    return d;
}
__device__ __forceinline__ float lo32(unsigned long long v) { return __uint_as_float((unsigned)v); }
__device__ __forceinline__ float hi32(unsigned long long v) { return __uint_as_float((unsigned)(v >> 32)); }

/* ------------------------------- FPS ------------------------------------ */
__global__ void __launch_bounds__(1024) fps_kernel(const float* __restrict__ xyz,
                                                   float* __restrict__ out_newxyz)
{
    const int b = blockIdx.x;
    const int t = threadIdx.x;
    const int lane = t & 31, wid = t >> 5;
    const float* X = xyz + (size_t)b*NN*3;

    float px[4], py[4], pz[4], dd[4];
#pragma unroll
    for (int j = 0; j < 4; j++) {
        int p = t + 1024*j;
        px[j] = X[p*3+0]; py[j] = X[p*3+1]; pz[j] = X[p*3+2];
        dd[j] = 1e10f;
    }
    __shared__ unsigned long long wb[32];
    int far = 0;

    for (int it = 0; it < SS; ++it) {
        float cx = X[far*3+0], cy = X[far*3+1], cz = X[far*3+2];
        if (t == 0) {
            int o = b*SS + it;
            out_newxyz[o*3+0] = cx; out_newxyz[o*3+1] = cy; out_newxyz[o*3+2] = cz;
            g_newxyz[o*3+0]  = cx; g_newxyz[o*3+1]  = cy; g_newxyz[o*3+2]  = cz;
        }
        unsigned long long best = 0ull;
#pragma unroll
        for (int j = 0; j < 4; j++) {
            float dx = px[j]-cx, dy = py[j]-cy, dz = pz[j]-cz;
            float d  = fmaf(dz, dz, fmaf(dy, dy, dx*dx));
            dd[j] = fminf(dd[j], d);
            int p = t + 1024*j;
            unsigned long long key =
                (((unsigned long long)__float_as_uint(dd[j])) << 32) | (unsigned)(NN-1-p);
            best = (key > best) ? key : best;
        }
#pragma unroll
        for (int o = 16; o; o >>= 1) {
            unsigned long long v = __shfl_xor_sync(0xffffffffu, best, o);
            if (v > best) best = v;
        }
        if (lane == 0) wb[wid] = best;
        __syncthreads();
        unsigned long long v = wb[lane];
#pragma unroll
        for (int o = 16; o; o >>= 1) {
            unsigned long long u = __shfl_xor_sync(0xffffffffu, v, o);
            if (u > v) v = u;
        }
        far = NN - 1 - (int)(v & 0xffffffffu);
        __syncthreads();
    }
}

/* ------------------------------- kNN ------------------------------------ */
__device__ __forceinline__ unsigned mono_f32(float v)
{
    unsigned u = __float_as_uint(v);
    return (u & 0x80000000u) ? ~u : (u | 0x80000000u);
}

__global__ void __launch_bounds__(128) knn_kernel(const float* __restrict__ xyz)
{
    const int q = blockIdx.x;
    const int b = q >> 10;
    const int t = threadIdx.x;
    __shared__ float d2s[NN];
    __shared__ unsigned long long lmin[128];
    __shared__ unsigned long long bestsh;
    const float* X = xyz + (size_t)b*NN*3;

    float qx = g_newxyz[q*3+0], qy = g_newxyz[q*3+1], qz = g_newxyz[q*3+2];
    float qq = qx*qx + qy*qy + qz*qz;

    for (int p = t; p < NN; p += 128) {
        float x = X[p*3+0], y = X[p*3+1], z = X[p*3+2];
        float pp  = x*x + y*y + z*z;
        float dot = qx*x + qy*y + qz*z;
        d2s[p] = qq + pp - 2.0f*dot;       /* same formula as reference sq_cdist */
    }
    __syncthreads();

    unsigned long long k = 0xffffffffffffffffull;
#pragma unroll 8
    for (int i = 0; i < 32; i++) {
        int p = t + 128*i;
        unsigned long long kk = (((unsigned long long)mono_f32(d2s[p])) << 32) | (unsigned)p;
        if (kk < k) k = kk;
    }
    lmin[t] = k;

    for (int r = 0; r < KMAX; r++) {
        __syncthreads();
        if (t < 32) {
            unsigned long long v = lmin[t];
            unsigned long long a = lmin[t+32]; if (a < v) v = a;
            a = lmin[t+64]; if (a < v) v = a;
            a = lmin[t+96]; if (a < v) v = a;
#pragma unroll
            for (int o = 16; o; o >>= 1) {
                unsigned long long u = __shfl_xor_sync(0xffffffffu, v, o);
                if (u < v) v = u;
            }
            if (t == 0) bestsh = v;
        }
        __syncthreads();
        unsigned long long w = bestsh;
        int p = (int)(w & 0xffffffffu);
        if (t == 0) g_knn[q*KMAX + r] = p;
        if ((p & 127) == t) {                 /* owner: invalidate + rescan */
            d2s[p] = __int_as_float(0x7f800000);
            unsigned long long nk = 0xffffffffffffffffull;
#pragma unroll 8
            for (int i = 0; i < 32; i++) {
                int pp2 = t + 128*i;
                unsigned long long kk =
                    (((unsigned long long)mono_f32(d2s[pp2])) << 32) | (unsigned)pp2;
                if (kk < nk) nk = kk;
            }
            lmin[t] = nk;
        }
    }
}

/* -------------------- conv1: gather + concat + 67->64 GEMM -------------- */
__global__ void __launch_bounds__(256) conv1_kernel(const float* __restrict__ xyz,
                                                    const float* __restrict__ feat,
                                                    const float* __restrict__ W, /* [64][67] */
                                                    int lgk)
{
    __shared__ float Xs[CIN][64];
    __shared__ float Ws[CIN][64];
    __shared__ float ssum[64], ssq[64];
    const int t = threadIdx.x;
    const int tile = blockIdx.x;

    for (int i = t; i < CIN*64; i += 256) {
        int in = i >> 6, o = i & 63;
        Ws[in][o] = W[o*CIN + in];
    }
    {
        const int lr = t >> 2, sub = t & 3;
        const int gr = tile*64 + lr;
        const int q  = gr >> lgk;
        const int j  = gr & ((1 << lgk) - 1);
        const int n  = g_knn[q*KMAX + j];
        const int b  = q >> 10;
        const float* fp = feat + ((size_t)(b*NN + n))*CF;
#pragma unroll
        for (int t4 = 0; t4 < 4; t4++) {
            int fi = sub*4 + t4;
            float4 v = *(const float4*)(fp + fi*4);
            Xs[3+fi*4+0][lr] = v.x; Xs[3+fi*4+1][lr] = v.y;
            Xs[3+fi*4+2][lr] = v.z; Xs[3+fi*4+3][lr] = v.w;
        }
        if (sub == 0) {
            const float* xp = xyz + (size_t)(b*NN + n)*3;
            Xs[0][lr] = xp[0] - g_newxyz[q*3+0];
            Xs[1][lr] = xp[1] - g_newxyz[q*3+1];
            Xs[2][lr] = xp[2] - g_newxyz[q*3+2];
        }
    }
    __syncthreads();

    const int rg = t & 15, cg = t >> 4;
    unsigned long long acc[4][2];
#pragma unroll
    for (int r = 0; r < 4; r++) { acc[r][0] = 0ull; acc[r][1] = 0ull; }

#pragma unroll 4
    for (int kk = 0; kk < CIN; kk++) {
        float4 a = *(const float4*)&Xs[kk][rg*4];
        ulonglong2 bp = *(const ulonglong2*)&Ws[kk][cg*4];
        unsigned long long a0 = dup2f(a.x), a1 = dup2f(a.y),
                           a2 = dup2f(a.z), a3 = dup2f(a.w);
        acc[0][0] = ffma2(a0, bp.x, acc[0][0]); acc[0][1] = ffma2(a0, bp.y, acc[0][1]);
        acc[1][0] = ffma2(a1, bp.x, acc[1][0]); acc[1][1] = ffma2(a1, bp.y, acc[1][1]);
        acc[2][0] = ffma2(a2, bp.x, acc[2][0]); acc[2][1] = ffma2(a2, bp.y, acc[2][1]);
        acc[3][0] = ffma2(a3, bp.x, acc[3][0]); acc[3][1] = ffma2(a3, bp.y, acc[3][1]);
    }

    const int gr0 = tile*64 + rg*4;
#pragma unroll
    for (int r = 0; r < 4; r++) {
        ulonglong2 o; o.x = acc[r][0]; o.y = acc[r][1];
        *(ulonglong2*)&g_buf1[(size_t)(gr0+r)*64 + cg*4] = o;
    }

    /* stats: unpack, reduce over 4 rows, xor-shuffle over 16 rg lanes */
    float s[4], sq[4];
#pragma unroll
    for (int c = 0; c < 4; c++) {
        float v0 = (c & 1) ? hi32(acc[0][c>>1]) : lo32(acc[0][c>>1]);
        float v1 = (c & 1) ? hi32(acc[1][c>>1]) : lo32(acc[1][c>>1]);
        float v2 = (c & 1) ? hi32(acc[2][c>>1]) : lo32(acc[2][c>>1]);
        float v3 = (c & 1) ? hi32(acc[3][c>>1]) : lo32(acc[3][c>>1]);
        s[c]  = v0 + v1 + v2 + v3;
        sq[c] = v0*v0 + v1*v1 + v2*v2 + v3*v3;
    }
#pragma unroll
    for (int o = 8; o; o >>= 1) {
#pragma unroll
        for (int c = 0; c < 4; c++) {
            s[c]  += __shfl_xor_sync(0xffffffffu, s[c],  o);
            sq[c] += __shfl_xor_sync(0xffffffffu, sq[c], o);
        }
    }
    if ((t & 15) == 0) {
#pragma unroll
        for (int c = 0; c < 4; c++) { ssum[cg*4+c] = s[c]; ssq[cg*4+c] = sq[c]; }
    }
    __syncthreads();
    if (t < 64) {
        atomicAdd(&g_sum[t], (double)ssum[t]);
        atomicAdd(&g_sq[t],  (double)ssq[t]);
    }
}

/* -------- conv2: BN+ReLU(load) + 64->64 GEMM -> g_buf2 ------------------ */
__global__ void __launch_bounds__(256) conv2_kernel(const float* __restrict__ W /* [64][64] */)
{
    __shared__ float Xs[64][64];
    __shared__ float Ws[64][64];
    __shared__ float sc[64], sh[64], ssum[64], ssq[64];
    const int t = threadIdx.x;
    const int tile = blockIdx.x;

    if (t < 64) { sc[t] = g_scl[t]; sh[t] = g_shf[t]; }
    __syncthreads();

    for (int i = t; i < 64*64; i += 256) {
        int in = i >> 6, o = i & 63;
        Ws[in][o] = W[(size_t)o*64 + in];
    }
    {
        const int lr = t >> 2, sub = t & 3;
        const size_t gr = (size_t)tile*64 + lr;
        const float* ip = g_buf1 + gr*64;
#pragma unroll
        for (int t4 = 0; t4 < 4; t4++) {
            int c0 = (sub*4 + t4)*4;
            float4 v = *(const float4*)(ip + c0);
            Xs[c0+0][lr] = fmaxf(fmaf(v.x, sc[c0+0], sh[c0+0]), 0.f);
            Xs[c0+1][lr] = fmaxf(fmaf(v.y, sc[c0+1], sh[c0+1]), 0.f);
            Xs[c0+2][lr] = fmaxf(fmaf(v.z, sc[c0+2], sh[c0+2]), 0.f);
            Xs[c0+3][lr] = fmaxf(fmaf(v.w, sc[c0+3], sh[c0+3]), 0.f);
        }
    }
    __syncthreads();

    const int rg = t & 15, cg = t >> 4;
    unsigned long long acc[4][2];
#pragma unroll
    for (int r = 0; r < 4; r++) { acc[r][0] = 0ull; acc[r][1] = 0ull; }

#pragma unroll 8
    for (int kk = 0; kk < 64; kk++) {
        float4 a = *(const float4*)&Xs[kk][rg*4];
        ulonglong2 bp = *(const ulonglong2*)&Ws[kk][cg*4];
        unsigned long long a0 = dup2f(a.x), a1 = dup2f(a.y),
                           a2 = dup2f(a.z), a3 = dup2f(a.w);
        acc[0][0] = ffma2(a0, bp.x, acc[0][0]); acc[0][1] = ffma2(a0, bp.y, acc[0][1]);
        acc[1][0] = ffma2(a1, bp.x, acc[1][0]); acc[1][1] = ffma2(a1, bp.y, acc[1][1]);
        acc[2][0] = ffma2(a2, bp.x, acc[2][0]); acc[2][1] = ffma2(a2, bp.y, acc[2][1]);
        acc[3][0] = ffma2(a3, bp.x, acc[3][0]); acc[3][1] = ffma2(a3, bp.y, acc[3][1]);
    }

    const size_t gr0 = (size_t)tile*64 + (size_t)rg*4;
#pragma unroll
    for (int r = 0; r < 4; r++) {
        ulonglong2 o; o.x = acc[r][0]; o.y = acc[r][1];
        *(ulonglong2*)&g_buf2[(gr0+r)*64 + cg*4] = o;
    }

    float s[4], sq[4];
#pragma unroll
    for (int c = 0; c < 4; c++) {
        float v0 = (c & 1) ? hi32(acc[0][c>>1]) : lo32(acc[0][c>>1]);
        float v1 = (c & 1) ? hi32(acc[1][c>>1]) : lo32(acc[1][c>>1]);
        float v2 = (c & 1) ? hi32(acc[2][c>>1]) : lo32(acc[2][c>>1]);
        float v3 = (c & 1) ? hi32(acc[3][c>>1]) : lo32(acc[3][c>>1]);
        s[c]  = v0 + v1 + v2 + v3;
        sq[c] = v0*v0 + v1*v1 + v2*v2 + v3*v3;
    }
#pragma unroll
    for (int o = 8; o; o >>= 1) {
#pragma unroll
        for (int c = 0; c < 4; c++) {
            s[c]  += __shfl_xor_sync(0xffffffffu, s[c],  o);
            sq[c] += __shfl_xor_sync(0xffffffffu, sq[c], o);
        }
    }
    if ((t & 15) == 0) {
#pragma unroll
        for (int c = 0; c < 4; c++) { ssum[cg*4+c] = s[c]; ssq[cg*4+c] = sq[c]; }
    }
    __syncthreads();
    if (t < 64) {
        atomicAdd(&g_sum[t], (double)ssum[t]);
        atomicAdd(&g_sq[t],  (double)ssq[t]);
    }
}

/* ---- conv3: BN+ReLU(load) + 64->128 GEMM + in-tile max/min over k ------- */
template<int K>
__global__ void __launch_bounds__(256) conv3_kernel(const float* __restrict__ W /* [128][64] */)
{
    __shared__ float Xs[64][64];
    __shared__ float Ws[64][64];
    __shared__ float sc[64], sh[64], ssum[64], ssq[64];
    const int t = threadIdx.x;
    const int tile   = blockIdx.x;
    const int colOff = blockIdx.y * 64;

    if (t < 64) { sc[t] = g_scl[t]; sh[t] = g_shf[t]; }
    __syncthreads();

    for (int i = t; i < 64*64; i += 256) {
        int in = i >> 6, o = i & 63;
        Ws[in][o] = W[(size_t)(colOff + o)*64 + in];
    }
    {
        const int lr = t >> 2, sub = t & 3;
        const size_t gr = (size_t)tile*64 + lr;
        const float* ip = g_buf2 + gr*64;
#pragma unroll
        for (int t4 = 0; t4 < 4; t4++) {
            int c0 = (sub*4 + t4)*4;
            float4 v = *(const float4*)(ip + c0);
            Xs[c0+0][lr] = fmaxf(fmaf(v.x, sc[c0+0], sh[c0+0]), 0.f);
            Xs[c0+1][lr] = fmaxf(fmaf(v.y, sc[c0+1], sh[c0+1]), 0.f);
            Xs[c0+2][lr] = fmaxf(fmaf(v.z, sc[c0+2], sh[c0+2]), 0.f);
            Xs[c0+3][lr] = fmaxf(fmaf(v.w, sc[c0+3], sh[c0+3]), 0.f);
        }
    }
    __syncthreads();

    const int rg = t & 15, cg = t >> 4;
    unsigned long long acc[4][2];
#pragma unroll
    for (int r = 0; r < 4; r++) { acc[r][0] = 0ull; acc[r][1] = 0ull; }

#pragma unroll 8
    for (int kk = 0; kk < 64; kk++) {
        float4 a = *(const float4*)&Xs[kk][rg*4];
        ulonglong2 bp = *(const ulonglong2*)&Ws[kk][cg*4];
        unsigned long long a0 = dup2f(a.x), a1 = dup2f(a.y),
                           a2 = dup2f(a.z), a3 = dup2f(a.w);
        acc[0][0] = ffma2(a0, bp.x, acc[0][0]); acc[0][1] = ffma2(a0, bp.y, acc[0][1]);
        acc[1][0] = ffma2(a1, bp.x, acc[1][0]); acc[1][1] = ffma2(a1, bp.y, acc[1][1]);
        acc[2][0] = ffma2(a2, bp.x, acc[2][0]); acc[2][1] = ffma2(a2, bp.y, acc[2][1]);
        acc[3][0] = ffma2(a3, bp.x, acc[3][0]); acc[3][1] = ffma2(a3, bp.y, acc[3][1]);
    }

    /* unpack: v[r][c] = pre-BN output (row tile*64+rg*4+r, col colOff+cg*4+c) */
    float v[4][4];
#pragma unroll
    for (int r = 0; r < 4; r++) {
        v[r][0] = lo32(acc[r][0]); v[r][1] = hi32(acc[r][0]);
        v[r][2] = lo32(acc[r][1]); v[r][3] = hi32(acc[r][1]);
    }

    /* stats */
    float s[4], sq[4];
#pragma unroll
    for (int c = 0; c < 4; c++) {
        s[c]  = v[0][c] + v[1][c] + v[2][c] + v[3][c];
        sq[c] = v[0][c]*v[0][c] + v[1][c]*v[1][c] + v[2][c]*v[2][c] + v[3][c]*v[3][c];
    }
#pragma unroll
    for (int o = 8; o; o >>= 1) {
#pragma unroll
        for (int c = 0; c < 4; c++) {
            s[c]  += __shfl_xor_sync(0xffffffffu, s[c],  o);
            sq[c] += __shfl_xor_sync(0xffffffffu, sq[c], o);
        }
    }
    if ((t & 15) == 0) {
#pragma unroll
        for (int c = 0; c < 4; c++) { ssum[cg*4+c] = s[c]; ssq[cg*4+c] = sq[c]; }
    }

    /* per-(q,c) max/min over the K neighbors within this tile.
       Rows of one q are contiguous; K/4 consecutive rg lanes form one group. */
    constexpr int GL = K / 4;              /* lanes per q-group (4, 8 or 16) */
    float mx[4], mn[4];
#pragma unroll
    for (int c = 0; c < 4; c++) {
        mx[c] = fmaxf(fmaxf(v[0][c], v[1][c]), fmaxf(v[2][c], v[3][c]));
        mn[c] = fminf(fminf(v[0][c], v[1][c]), fminf(v[2][c], v[3][c]));
    }
#pragma unroll
    for (int o = GL/2; o; o >>= 1) {
#pragma unroll
        for (int c = 0; c < 4; c++) {
            mx[c] = fmaxf(mx[c], __shfl_xor_sync(0xffffffffu, mx[c], o));
            mn[c] = fminf(mn[c], __shfl_xor_sync(0xffffffffu, mn[c], o));
        }
    }
    if ((rg & (GL - 1)) == 0) {
        const int q = tile * (64 / K) + (rg * 4) / K;
#pragma unroll
        for (int c = 0; c < 4; c++) {
            g_max[q*128 + colOff + cg*4 + c] = mx[c];
            g_min[q*128 + colOff + cg*4 + c] = mn[c];
        }
    }

    __syncthreads();
    if (t < 64) {
        atomicAdd(&g_sum[colOff + t], (double)ssum[t]);
        atomicAdd(&g_sq[colOff + t],  (double)ssq[t]);
    }
}

/* -------------- stats: sums -> (scale, shift); re-zero accumulators ------ */
__global__ void stats_kernel(const float* __restrict__ gamma,
                             const float* __restrict__ beta,
                             int C, double invn)
{
    int c = threadIdx.x;
    if (c < C) {
        double s = g_sum[c], q = g_sq[c];
        double mu = s * invn;
        double var = q * invn - mu * mu;
        float rstd = rsqrtf((float)var + 1e-5f);
        float scl = gamma[c] * rstd;
        g_scl[c] = scl;
        g_shf[c] = beta[c] - (float)mu * scl;
        g_sum[c] = 0.0;
        g_sq[c]  = 0.0;
    }
}

/* -------- finalize: BN(+sign-aware max/min) + ReLU -> out ---------------- */
__global__ void __launch_bounds__(128) finalize_kernel(float* __restrict__ out, int base)
{
    const int q = blockIdx.x;
    const int c = threadIdx.x;
    const float scl = g_scl[c], shf = g_shf[c];
    float sel = (scl >= 0.f) ? g_max[q*128 + c] : g_min[q*128 + c];
    out[(size_t)NQ*3 + (size_t)q*384 + base + c] = fmaxf(fmaf(sel, scl, shf), 0.f);
}

/* ------------------------------ driver ----------------------------------- */
extern "C" void kernel_launch(void* const* d_in, const int* in_sizes, int n_in,
                              void* d_out, int out_size)
{
    const float* xyz  = (const float*)d_in[0];
    const float* feat = (const float*)d_in[1];
    const float* w0   = (const float*)d_in[2];
    const float* w1   = (const float*)d_in[3];
    const float* w2   = (const float*)d_in[4];
    const float* g0   = (const float*)d_in[5];
    const float* g1   = (const float*)d_in[6];
    const float* g2   = (const float*)d_in[7];
    const float* b0   = (const float*)d_in[8];
    const float* b1   = (const float*)d_in[9];
    const float* b2   = (const float*)d_in[10];
    float* out = (float*)d_out;

    fps_kernel<<<BB, 1024>>>(xyz, out);
    knn_kernel<<<NQ, 128>>>(xyz);

    const int KS[3]  = {16, 32, 64};
    const int LGK[3] = {4, 5, 6};
    for (int s = 0; s < 3; s++) {
        const int k = KS[s];
        const int R = NQ * k;
        const double invn = 1.0 / (double)R;

        conv1_kernel<<<R/64, 256>>>(xyz, feat, w0 + (size_t)s*64*CIN, LGK[s]);
        stats_kernel<<<1, 128>>>(g0 + s*64, b0 + s*64, 64, invn);

        conv2_kernel<<<R/64, 256>>>(w1 + (size_t)s*64*64);
        stats_kernel<<<1, 128>>>(g1 + s*64, b1 + s*64, 64, invn);

        if (k == 16)      conv3_kernel<16><<<dim3(R/64, 2), 256>>>(w2 + (size_t)s*128*64);
        else if (k == 32) conv3_kernel<32><<<dim3(R/64, 2), 256>>>(w2 + (size_t)s*128*64);
        else              conv3_kernel<64><<<dim3(R/64, 2), 256>>>(w2 + (size_t)s*128*64);
        stats_kernel<<<1, 128>>>(g2 + s*128, b2 + s*128, 128, invn);

        finalize_kernel<<<NQ, 128>>>(out, s*128);
    }
}

// round 4
// speedup vs baseline: 1.4355x; 1.1288x over previous
#include <cuda_runtime.h>

#define BB 16
#define NN 4096
#define SS 1024
#define NQ (BB*SS)        /* 16384 queries */
#define KMAX 64
#define CIN 67
#define CF  64
#define XP  132           /* Xs row pitch (floats): mult of 4, not mult of 32 */

/* ---------------- scratch (device globals; no allocation allowed) -------- */
__device__ int    g_knn[NQ*KMAX];
__device__ float  g_newxyz[NQ*3];
__device__ float  g_buf1[(size_t)NQ*KMAX*64];
__device__ float  g_buf2[(size_t)NQ*KMAX*64];
__device__ float  g_max[NQ*128];
__device__ float  g_min[NQ*128];
__device__ double g_sum[128];
__device__ double g_sq[128];
__device__ float  g_scl[128];
__device__ float  g_shf[128];

/* ---------------- packed f32x2 helpers (FFMA2 = full-rate fp32) ---------- */
__device__ __forceinline__ unsigned long long dup2f(float v)
{
    unsigned long long r;
    asm("mov.b64 %0, {%1, %1};" : "=l"(r) : "f"(v));
    return r;
}
__device__ __forceinline__ unsigned long long ffma2(unsigned long long a,
                                                    unsigned long long b,
                                                    unsigned long long c)
{
    unsigned long long d;
    asm("fma.rn.f32x2 %0, %1, %2, %3;" : "=l"(d) : "l"(a), "l"(b), "l"(c));
    return d;
}
__device__ __forceinline__ float lo32(unsigned long long v) { return __uint_as_float((unsigned)v); }
__device__ __forceinline__ float hi32(unsigned long long v) { return __uint_as_float((unsigned)(v >> 32)); }

/* --------------------------- init (also shifts ncu) ---------------------- */
__global__ void init_kernel()
{
    int t = threadIdx.x;
    if (t < 128) { g_sum[t] = 0.0; g_sq[t] = 0.0; }
}

/* ------------------------------- FPS ------------------------------------ */
__global__ void __launch_bounds__(1024) fps_kernel(const float* __restrict__ xyz,
                                                   float* __restrict__ out_newxyz)
{
    const int b = blockIdx.x;
    const int t = threadIdx.x;
    const int lane = t & 31, wid = t >> 5;
    const float* X = xyz + (size_t)b*NN*3;

    float px[4], py[4], pz[4], dd[4];
#pragma unroll
    for (int j = 0; j < 4; j++) {
        int p = t + 1024*j;
        px[j] = X[p*3+0]; py[j] = X[p*3+1]; pz[j] = X[p*3+2];
        dd[j] = 1e10f;
    }
    __shared__ unsigned long long wb[32];
    int far = 0;

    for (int it = 0; it < SS; ++it) {
        float cx = X[far*3+0], cy = X[far*3+1], cz = X[far*3+2];
        if (t == 0) {
            int o = b*SS + it;
            out_newxyz[o*3+0] = cx; out_newxyz[o*3+1] = cy; out_newxyz[o*3+2] = cz;
            g_newxyz[o*3+0]  = cx; g_newxyz[o*3+1]  = cy; g_newxyz[o*3+2]  = cz;
        }
        unsigned long long best = 0ull;
#pragma unroll
        for (int j = 0; j < 4; j++) {
            float dx = px[j]-cx, dy = py[j]-cy, dz = pz[j]-cz;
            float d  = fmaf(dz, dz, fmaf(dy, dy, dx*dx));
            dd[j] = fminf(dd[j], d);
            int p = t + 1024*j;
            unsigned long long key =
                (((unsigned long long)__float_as_uint(dd[j])) << 32) | (unsigned)(NN-1-p);
            best = (key > best) ? key : best;
        }
#pragma unroll
        for (int o = 16; o; o >>= 1) {
            unsigned long long v = __shfl_xor_sync(0xffffffffu, best, o);
            if (v > best) best = v;
        }
        if (lane == 0) wb[wid] = best;
        __syncthreads();
        unsigned long long v = wb[lane];
#pragma unroll
        for (int o = 16; o; o >>= 1) {
            unsigned long long u = __shfl_xor_sync(0xffffffffu, v, o);
            if (u > v) v = u;
        }
        far = NN - 1 - (int)(v & 0xffffffffu);
        __syncthreads();
    }
}

/* ------------------------------- kNN ------------------------------------ */
__device__ __forceinline__ unsigned mono_f32(float v)
{
    unsigned u = __float_as_uint(v);
    return (u & 0x80000000u) ? ~u : (u | 0x80000000u);
}

__global__ void __launch_bounds__(128) knn_kernel(const float* __restrict__ xyz)
{
    const int q = blockIdx.x;
    const int b = q >> 10;
    const int t = threadIdx.x;
    __shared__ float d2s[NN];
    __shared__ unsigned long long lmin[128];
    __shared__ unsigned long long bestsh;
    const float* X = xyz + (size_t)b*NN*3;

    float qx = g_newxyz[q*3+0], qy = g_newxyz[q*3+1], qz = g_newxyz[q*3+2];
    float qq = qx*qx + qy*qy + qz*qz;

    for (int p = t; p < NN; p += 128) {
        float x = X[p*3+0], y = X[p*3+1], z = X[p*3+2];
        float pp  = x*x + y*y + z*z;
        float dot = qx*x + qy*y + qz*z;
        d2s[p] = qq + pp - 2.0f*dot;       /* same formula as reference sq_cdist */
    }
    __syncthreads();

    unsigned long long k = 0xffffffffffffffffull;
#pragma unroll 8
    for (int i = 0; i < 32; i++) {
        int p = t + 128*i;
        unsigned long long kk = (((unsigned long long)mono_f32(d2s[p])) << 32) | (unsigned)p;
        if (kk < k) k = kk;
    }
    lmin[t] = k;

    for (int r = 0; r < KMAX; r++) {
        __syncthreads();
        if (t < 32) {
            unsigned long long v = lmin[t];
            unsigned long long a = lmin[t+32]; if (a < v) v = a;
            a = lmin[t+64]; if (a < v) v = a;
            a = lmin[t+96]; if (a < v) v = a;
#pragma unroll
            for (int o = 16; o; o >>= 1) {
                unsigned long long u = __shfl_xor_sync(0xffffffffu, v, o);
                if (u < v) v = u;
            }
            if (t == 0) bestsh = v;
        }
        __syncthreads();
        unsigned long long w = bestsh;
        int p = (int)(w & 0xffffffffu);
        if (t == 0) g_knn[q*KMAX + r] = p;
        if ((p & 127) == t) {                 /* owner: invalidate + rescan */
            d2s[p] = __int_as_float(0x7f800000);
            unsigned long long nk = 0xffffffffffffffffull;
#pragma unroll 8
            for (int i = 0; i < 32; i++) {
                int pp2 = t + 128*i;
                unsigned long long kk =
                    (((unsigned long long)mono_f32(d2s[pp2])) << 32) | (unsigned)pp2;
                if (kk < nk) nk = kk;
            }
            lmin[t] = nk;
        }
    }
}

/* ------------- conv1: gather + concat + 67->64, 128-row tiles ------------ */
__global__ void __launch_bounds__(256) conv1_kernel(const float* __restrict__ xyz,
                                                    const float* __restrict__ feat,
                                                    const float* __restrict__ W, /* [64][67] */
                                                    int lgk)
{
    extern __shared__ float dyn[];
    float* Xs = dyn;                 /* [CIN][XP] */
    float* Ws = dyn + CIN*XP;        /* [CIN][64] */
    __shared__ float ssum[64], ssq[64];
    const int t = threadIdx.x;
    const int tile = blockIdx.x;

    for (int i = t; i < CIN*64; i += 256) {
        int in = i >> 6, o = i & 63;
        Ws[in*64 + o] = W[o*CIN + in];
    }
    {
        const int lr = t >> 1, sub = t & 1;
        const int gr = tile*128 + lr;
        const int q  = gr >> lgk;
        const int j  = gr & ((1 << lgk) - 1);
        const int n  = g_knn[q*KMAX + j];
        const int b  = q >> 10;
        const float* fp = feat + ((size_t)(b*NN + n))*CF + sub*32;
#pragma unroll
        for (int t4 = 0; t4 < 8; t4++) {
            float4 v = *(const float4*)(fp + t4*4);
            int c0 = 3 + sub*32 + t4*4;
            Xs[(c0+0)*XP + lr] = v.x; Xs[(c0+1)*XP + lr] = v.y;
            Xs[(c0+2)*XP + lr] = v.z; Xs[(c0+3)*XP + lr] = v.w;
        }
        if (sub == 0) {
            const float* xp = xyz + (size_t)(b*NN + n)*3;
            Xs[0*XP + lr] = xp[0] - g_newxyz[q*3+0];
            Xs[1*XP + lr] = xp[1] - g_newxyz[q*3+1];
            Xs[2*XP + lr] = xp[2] - g_newxyz[q*3+2];
        }
    }
    __syncthreads();

    const int rg = t & 15, cg = t >> 4;
    unsigned long long acc[8][2];
#pragma unroll
    for (int r = 0; r < 8; r++) { acc[r][0] = 0ull; acc[r][1] = 0ull; }

#pragma unroll 2
    for (int kk = 0; kk < CIN; kk++) {
        float4 x0 = *(const float4*)&Xs[kk*XP + rg*8];
        float4 x1 = *(const float4*)&Xs[kk*XP + rg*8 + 4];
        ulonglong2 bp = *(const ulonglong2*)&Ws[kk*64 + cg*4];
        float xv[8] = {x0.x, x0.y, x0.z, x0.w, x1.x, x1.y, x1.z, x1.w};
#pragma unroll
        for (int r = 0; r < 8; r++) {
            unsigned long long a = dup2f(xv[r]);
            acc[r][0] = ffma2(a, bp.x, acc[r][0]);
            acc[r][1] = ffma2(a, bp.y, acc[r][1]);
        }
    }

    const int gr0 = tile*128 + rg*8;
#pragma unroll
    for (int r = 0; r < 8; r++) {
        ulonglong2 o; o.x = acc[r][0]; o.y = acc[r][1];
        *(ulonglong2*)&g_buf1[(size_t)(gr0+r)*64 + cg*4] = o;
    }

#pragma unroll
    for (int c = 0; c < 4; c++) {
        float s = 0.f, sq = 0.f;
#pragma unroll
        for (int r = 0; r < 8; r++) {
            float v = (c & 1) ? hi32(acc[r][c>>1]) : lo32(acc[r][c>>1]);
            s += v; sq = fmaf(v, v, sq);
        }
#pragma unroll
        for (int o = 8; o; o >>= 1) {
            s  += __shfl_xor_sync(0xffffffffu, s,  o);
            sq += __shfl_xor_sync(0xffffffffu, sq, o);
        }
        if (rg == 0) { ssum[cg*4+c] = s; ssq[cg*4+c] = sq; }
    }
    __syncthreads();
    if (t < 64) {
        atomicAdd(&g_sum[t], (double)ssum[t]);
        atomicAdd(&g_sq[t],  (double)ssq[t]);
    }
}

/* -------- conv2: BN+ReLU(load) + 64->64, 128-row tiles ------------------ */
__global__ void __launch_bounds__(256) conv2_kernel(const float* __restrict__ W /* [64][64] */)
{
    extern __shared__ float dyn[];
    float* Xs = dyn;                 /* [64][XP] */
    float* Ws = dyn + 64*XP;         /* [64][64] */
    __shared__ float sc[64], sh[64], ssum[64], ssq[64];
    const int t = threadIdx.x;
    const int tile = blockIdx.x;

    if (t < 64) { sc[t] = g_scl[t]; sh[t] = g_shf[t]; }
    __syncthreads();

    for (int i = t; i < 64*64; i += 256) {
        int in = i >> 6, o = i & 63;
        Ws[in*64 + o] = W[(size_t)o*64 + in];
    }
    {
        const int lr = t >> 1, sub = t & 1;
        const float* ip = g_buf1 + ((size_t)tile*128 + lr)*64 + sub*32;
#pragma unroll
        for (int t4 = 0; t4 < 8; t4++) {
            float4 v = *(const float4*)(ip + t4*4);
            int c0 = sub*32 + t4*4;
            Xs[(c0+0)*XP + lr] = fmaxf(fmaf(v.x, sc[c0+0], sh[c0+0]), 0.f);
            Xs[(c0+1)*XP + lr] = fmaxf(fmaf(v.y, sc[c0+1], sh[c0+1]), 0.f);
            Xs[(c0+2)*XP + lr] = fmaxf(fmaf(v.z, sc[c0+2], sh[c0+2]), 0.f);
            Xs[(c0+3)*XP + lr] = fmaxf(fmaf(v.w, sc[c0+3], sh[c0+3]), 0.f);
        }
    }
    __syncthreads();

    const int rg = t & 15, cg = t >> 4;
    unsigned long long acc[8][2];
#pragma unroll
    for (int r = 0; r < 8; r++) { acc[r][0] = 0ull; acc[r][1] = 0ull; }

#pragma unroll 4
    for (int kk = 0; kk < 64; kk++) {
        float4 x0 = *(const float4*)&Xs[kk*XP + rg*8];
        float4 x1 = *(const float4*)&Xs[kk*XP + rg*8 + 4];
        ulonglong2 bp = *(const ulonglong2*)&Ws[kk*64 + cg*4];
        float xv[8] = {x0.x, x0.y, x0.z, x0.w, x1.x, x1.y, x1.z, x1.w};
#pragma unroll
        for (int r = 0; r < 8; r++) {
            unsigned long long a = dup2f(xv[r]);
            acc[r][0] = ffma2(a, bp.x, acc[r][0]);
            acc[r][1] = ffma2(a, bp.y, acc[r][1]);
        }
    }

    const size_t gr0 = (size_t)tile*128 + rg*8;
#pragma unroll
    for (int r = 0; r < 8; r++) {
        ulonglong2 o; o.x = acc[r][0]; o.y = acc[r][1];
        *(ulonglong2*)&g_buf2[(gr0+r)*64 + cg*4] = o;
    }

#pragma unroll
    for (int c = 0; c < 4; c++) {
        float s = 0.f, sq = 0.f;
#pragma unroll
        for (int r = 0; r < 8; r++) {
            float v = (c & 1) ? hi32(acc[r][c>>1]) : lo32(acc[r][c>>1]);
            s += v; sq = fmaf(v, v, sq);
        }
#pragma unroll
        for (int o = 8; o; o >>= 1) {
            s  += __shfl_xor_sync(0xffffffffu, s,  o);
            sq += __shfl_xor_sync(0xffffffffu, sq, o);
        }
        if (rg == 0) { ssum[cg*4+c] = s; ssq[cg*4+c] = sq; }
    }
    __syncthreads();
    if (t < 64) {
        atomicAdd(&g_sum[t], (double)ssum[t]);
        atomicAdd(&g_sq[t],  (double)ssq[t]);
    }
}

/* ---- conv3: BN+ReLU(load) + 64->128 (all cols) + in-tile max/min -------- */
template<int K>
__global__ void __launch_bounds__(256) conv3_kernel(const float* __restrict__ W /* [128][64] */)
{
    extern __shared__ float dyn[];
    float* Xs = dyn;                 /* [64][XP]  */
    float* Ws = dyn + 64*XP;         /* [64][128] */
    __shared__ float sc[64], sh[64], ssum[128], ssq[128];
    const int t = threadIdx.x;
    const int tile = blockIdx.x;

    if (t < 64) { sc[t] = g_scl[t]; sh[t] = g_shf[t]; }
    __syncthreads();

    for (int i = t; i < 64*128; i += 256) {
        int in = i >> 7, o = i & 127;
        Ws[in*128 + o] = W[(size_t)o*64 + in];
    }
    {
        const int lr = t >> 1, sub = t & 1;
        const float* ip = g_buf2 + ((size_t)tile*128 + lr)*64 + sub*32;
#pragma unroll
        for (int t4 = 0; t4 < 8; t4++) {
            float4 v = *(const float4*)(ip + t4*4);
            int c0 = sub*32 + t4*4;
            Xs[(c0+0)*XP + lr] = fmaxf(fmaf(v.x, sc[c0+0], sh[c0+0]), 0.f);
            Xs[(c0+1)*XP + lr] = fmaxf(fmaf(v.y, sc[c0+1], sh[c0+1]), 0.f);
            Xs[(c0+2)*XP + lr] = fmaxf(fmaf(v.z, sc[c0+2], sh[c0+2]), 0.f);
            Xs[(c0+3)*XP + lr] = fmaxf(fmaf(v.w, sc[c0+3], sh[c0+3]), 0.f);
        }
    }
    __syncthreads();

    const int rg = t & 15, cg = t >> 4;
    unsigned long long acc[8][4];
#pragma unroll
    for (int r = 0; r < 8; r++)
#pragma unroll
        for (int c = 0; c < 4; c++) acc[r][c] = 0ull;

#pragma unroll 4
    for (int kk = 0; kk < 64; kk++) {
        float4 x0 = *(const float4*)&Xs[kk*XP + rg*8];
        float4 x1 = *(const float4*)&Xs[kk*XP + rg*8 + 4];
        ulonglong2 b0 = *(const ulonglong2*)&Ws[kk*128 + cg*8];
        ulonglong2 b1 = *(const ulonglong2*)&Ws[kk*128 + cg*8 + 4];
        float xv[8] = {x0.x, x0.y, x0.z, x0.w, x1.x, x1.y, x1.z, x1.w};
#pragma unroll
        for (int r = 0; r < 8; r++) {
            unsigned long long a = dup2f(xv[r]);
            acc[r][0] = ffma2(a, b0.x, acc[r][0]);
            acc[r][1] = ffma2(a, b0.y, acc[r][1]);
            acc[r][2] = ffma2(a, b1.x, acc[r][2]);
            acc[r][3] = ffma2(a, b1.y, acc[r][3]);
        }
    }

    /* per-channel: stats + per-query max/min (query = K consecutive rows;
       thread's 8 rows lie inside one query since K>=16 and tiles align) */
    constexpr int GL = K / 8;                 /* rg lanes per query group */
    const int q = tile * (128 / K) + (rg * 8) / K;
#pragma unroll
    for (int c = 0; c < 8; c++) {
        float s = 0.f, sq = 0.f, mx = -3.4e38f, mn = 3.4e38f;
#pragma unroll
        for (int r = 0; r < 8; r++) {
            float v = (c & 1) ? hi32(acc[r][c>>1]) : lo32(acc[r][c>>1]);
            s += v; sq = fmaf(v, v, sq);
            mx = fmaxf(mx, v); mn = fminf(mn, v);
        }
#pragma unroll
        for (int o = 8; o; o >>= 1) {
            s  += __shfl_xor_sync(0xffffffffu, s,  o);
            sq += __shfl_xor_sync(0xffffffffu, sq, o);
        }
#pragma unroll
        for (int o = GL/2; o; o >>= 1) {
            mx = fmaxf(mx, __shfl_xor_sync(0xffffffffu, mx, o));
            mn = fminf(mn, __shfl_xor_sync(0xffffffffu, mn, o));
        }
        if (rg == 0) { ssum[cg*8+c] = s; ssq[cg*8+c] = sq; }
        if ((rg & (GL - 1)) == 0) {
            g_max[q*128 + cg*8 + c] = mx;
            g_min[q*128 + cg*8 + c] = mn;
        }
    }
    __syncthreads();
    if (t < 128) {
        atomicAdd(&g_sum[t], (double)ssum[t]);
        atomicAdd(&g_sq[t],  (double)ssq[t]);
    }
}

/* -------------- stats: sums -> (scale, shift); re-zero accumulators ------ */
__global__ void stats_kernel(const float* __restrict__ gamma,
                             const float* __restrict__ beta,
                             int C, double invn)
{
    int c = threadIdx.x;
    if (c < C) {
        double s = g_sum[c], q = g_sq[c];
        double mu = s * invn;
        double var = q * invn - mu * mu;
        float rstd = rsqrtf((float)var + 1e-5f);
        float scl = gamma[c] * rstd;
        g_scl[c] = scl;
        g_shf[c] = beta[c] - (float)mu * scl;
        g_sum[c] = 0.0;
        g_sq[c]  = 0.0;
    }
}

/* -------- finalize: BN(+sign-aware max/min) + ReLU -> out ---------------- */
__global__ void __launch_bounds__(128) finalize_kernel(float* __restrict__ out, int base)
{
    const int q = blockIdx.x;
    const int c = threadIdx.x;
    const float scl = g_scl[c], shf = g_shf[c];
    float sel = (scl >= 0.f) ? g_max[q*128 + c] : g_min[q*128 + c];
    out[(size_t)NQ*3 + (size_t)q*384 + base + c] = fmaxf(fmaf(sel, scl, shf), 0.f);
}

/* ------------------------------ driver ----------------------------------- */
extern "C" void kernel_launch(void* const* d_in, const int* in_sizes, int n_in,
                              void* d_out, int out_size)
{
    const float* xyz  = (const float*)d_in[0];
    const float* feat = (const float*)d_in[1];
    const float* w0   = (const float*)d_in[2];
    const float* w1   = (const float*)d_in[3];
    const float* w2   = (const float*)d_in[4];
    const float* g0   = (const float*)d_in[5];
    const float* g1   = (const float*)d_in[6];
    const float* g2   = (const float*)d_in[7];
    const float* b0   = (const float*)d_in[8];
    const float* b1   = (const float*)d_in[9];
    const float* b2   = (const float*)d_in[10];
    float* out = (float*)d_out;

    const int SM1 = (CIN*XP + CIN*64) * 4;   /* 52528 B */
    const int SM2 = (64*XP + 64*64) * 4;     /* 50176 B */
    const int SM3 = (64*XP + 64*128) * 4;    /* 66560 B */
    cudaFuncSetAttribute(conv1_kernel, cudaFuncAttributeMaxDynamicSharedMemorySize, SM1);
    cudaFuncSetAttribute(conv2_kernel, cudaFuncAttributeMaxDynamicSharedMemorySize, SM2);
    cudaFuncSetAttribute(conv3_kernel<16>, cudaFuncAttributeMaxDynamicSharedMemorySize, SM3);
    cudaFuncSetAttribute(conv3_kernel<32>, cudaFuncAttributeMaxDynamicSharedMemorySize, SM3);
    cudaFuncSetAttribute(conv3_kernel<64>, cudaFuncAttributeMaxDynamicSharedMemorySize, SM3);

    init_kernel<<<1, 128>>>();
    fps_kernel<<<BB, 1024>>>(xyz, out);
    knn_kernel<<<NQ, 128>>>(xyz);

    const int KS[3]  = {16, 32, 64};
    const int LGK[3] = {4, 5, 6};
    for (int s = 0; s < 3; s++) {
        const int k = KS[s];
        const int R = NQ * k;
        const double invn = 1.0 / (double)R;

        conv1_kernel<<<R/128, 256, SM1>>>(xyz, feat, w0 + (size_t)s*64*CIN, LGK[s]);
        stats_kernel<<<1, 128>>>(g0 + s*64, b0 + s*64, 64, invn);

        conv2_kernel<<<R/128, 256, SM2>>>(w1 + (size_t)s*64*64);
        stats_kernel<<<1, 128>>>(g1 + s*64, b1 + s*64, 64, invn);

        if (k == 16)      conv3_kernel<16><<<R/128, 256, SM3>>>(w2 + (size_t)s*128*64);
        else if (k == 32) conv3_kernel<32><<<R/128, 256, SM3>>>(w2 + (size_t)s*128*64);
        else              conv3_kernel<64><<<R/128, 256, SM3>>>(w2 + (size_t)s*128*64);
        stats_kernel<<<1, 128>>>(g2 + s*128, b2 + s*128, 128, invn);

        finalize_kernel<<<NQ, 128>>>(out, s*128);
    }
}

// round 7
// speedup vs baseline: 1.9590x; 1.3647x over previous
#include <cuda_runtime.h>
#include <cuda_bf16.h>
#include <mma.h>
#include <cstdint>

using namespace nvcuda;

#define BB 16
#define NN 4096
#define SS 1024
#define NQ (BB*SS)
#define KMAX 64
#define CIN 67
#define CF  64

/* ---------------- scratch (device globals; no allocation allowed) -------- */
__device__ int    g_knn[NQ*KMAX];
__device__ float  g_newxyz[NQ*3];
__device__ float  g_buf1[(size_t)NQ*KMAX*64];
__device__ float  g_buf2[(size_t)NQ*KMAX*64];
__device__ float  g_max[NQ*128];
__device__ float  g_min[NQ*128];
__device__ double g_sum[128];
__device__ double g_sq[128];
__device__ float  g_scl[128];
__device__ float  g_shf[128];

/* split a,b (fp32) into packed bf16 hi-pair and lo-pair (a in low 16 bits) */
__device__ __forceinline__ void split2(float a, float b, unsigned &hi, unsigned &lo)
{
    __nv_bfloat16 ah = __float2bfloat16(a), bh = __float2bfloat16(b);
    float ar = a - __bfloat162float(ah), br = b - __bfloat162float(bh);
    __nv_bfloat16 al = __float2bfloat16(ar), bl = __float2bfloat16(br);
    hi = (unsigned)__bfloat16_as_ushort(ah) | ((unsigned)__bfloat16_as_ushort(bh) << 16);
    lo = (unsigned)__bfloat16_as_ushort(al) | ((unsigned)__bfloat16_as_ushort(bl) << 16);
}

/* --------------------------- init ---------------------------------------- */
__global__ void init_kernel()
{
    int t = threadIdx.x;
    if (t < 128) { g_sum[t] = 0.0; g_sq[t] = 0.0; }
}

/* ------------------------------- FPS ------------------------------------ */
__global__ void __launch_bounds__(1024) fps_kernel(const float* __restrict__ xyz,
                                                   float* __restrict__ out_newxyz)
{
    const int b = blockIdx.x;
    const int t = threadIdx.x;
    const int lane = t & 31, wid = t >> 5;
    const float* X = xyz + (size_t)b*NN*3;

    float px[4], py[4], pz[4], dd[4];
#pragma unroll
    for (int j = 0; j < 4; j++) {
        int p = t + 1024*j;
        px[j] = X[p*3+0]; py[j] = X[p*3+1]; pz[j] = X[p*3+2];
        dd[j] = 1e10f;
    }
    __shared__ unsigned long long wb[32];
    int far = 0;

    for (int it = 0; it < SS; ++it) {
        float cx = X[far*3+0], cy = X[far*3+1], cz = X[far*3+2];
        if (t == 0) {
            int o = b*SS + it;
            out_newxyz[o*3+0] = cx; out_newxyz[o*3+1] = cy; out_newxyz[o*3+2] = cz;
            g_newxyz[o*3+0]  = cx; g_newxyz[o*3+1]  = cy; g_newxyz[o*3+2]  = cz;
        }
        unsigned long long best = 0ull;
#pragma unroll
        for (int j = 0; j < 4; j++) {
            float dx = px[j]-cx, dy = py[j]-cy, dz = pz[j]-cz;
            float d  = fmaf(dz, dz, fmaf(dy, dy, dx*dx));
            dd[j] = fminf(dd[j], d);
            int p = t + 1024*j;
            unsigned long long key =
                (((unsigned long long)__float_as_uint(dd[j])) << 32) | (unsigned)(NN-1-p);
            best = (key > best) ? key : best;
        }
#pragma unroll
        for (int o = 16; o; o >>= 1) {
            unsigned long long v = __shfl_xor_sync(0xffffffffu, best, o);
            if (v > best) best = v;
        }
        if (lane == 0) wb[wid] = best;
        __syncthreads();
        unsigned long long v = wb[lane];
#pragma unroll
        for (int o = 16; o; o >>= 1) {
            unsigned long long u = __shfl_xor_sync(0xffffffffu, v, o);
            if (u > v) v = u;
        }
        far = NN - 1 - (int)(v & 0xffffffffu);
        __syncthreads();
    }
}

/* ------------------------------- kNN ------------------------------------ */
__device__ __forceinline__ unsigned mono_f32(float v)
{
    unsigned u = __float_as_uint(v);
    return (u & 0x80000000u) ? ~u : (u | 0x80000000u);
}

__global__ void __launch_bounds__(128) knn_kernel(const float* __restrict__ xyz)
{
    const int q = blockIdx.x;
    const int b = q >> 10;
    const int t = threadIdx.x;
    __shared__ float d2s[NN];
    __shared__ unsigned long long lmin[128];
    __shared__ unsigned long long bestsh;
    const float* X = xyz + (size_t)b*NN*3;

    float qx = g_newxyz[q*3+0], qy = g_newxyz[q*3+1], qz = g_newxyz[q*3+2];
    float qq = qx*qx + qy*qy + qz*qz;

    for (int p = t; p < NN; p += 128) {
        float x = X[p*3+0], y = X[p*3+1], z = X[p*3+2];
        float pp  = x*x + y*y + z*z;
        float dot = qx*x + qy*y + qz*z;
        d2s[p] = qq + pp - 2.0f*dot;
    }
    __syncthreads();

    unsigned long long k = 0xffffffffffffffffull;
#pragma unroll 8
    for (int i = 0; i < 32; i++) {
        int p = t + 128*i;
        unsigned long long kk = (((unsigned long long)mono_f32(d2s[p])) << 32) | (unsigned)p;
        if (kk < k) k = kk;
    }
    lmin[t] = k;

    for (int r = 0; r < KMAX; r++) {
        __syncthreads();
        if (t < 32) {
            unsigned long long v = lmin[t];
            unsigned long long a = lmin[t+32]; if (a < v) v = a;
            a = lmin[t+64]; if (a < v) v = a;
            a = lmin[t+96]; if (a < v) v = a;
#pragma unroll
            for (int o = 16; o; o >>= 1) {
                unsigned long long u = __shfl_xor_sync(0xffffffffu, v, o);
                if (u < v) v = u;
            }
            if (t == 0) bestsh = v;
        }
        __syncthreads();
        unsigned long long w = bestsh;
        int p = (int)(w & 0xffffffffu);
        if (t == 0) g_knn[q*KMAX + r] = p;
        if ((p & 127) == t) {
            d2s[p] = __int_as_float(0x7f800000);
            unsigned long long nk = 0xffffffffffffffffull;
#pragma unroll 8
            for (int i = 0; i < 32; i++) {
                int pp2 = t + 128*i;
                unsigned long long kk =
                    (((unsigned long long)mono_f32(d2s[pp2])) << 32) | (unsigned)pp2;
                if (kk < nk) nk = kk;
            }
            lmin[t] = nk;
        }
    }
}

/* ================== WMMA bf16 (hi/lo split) conv kernels ================= */
/* channel order for conv1: feat 0..63, xyz 64..66, zero-pad 67..79          */

#define LD1 88          /* conv1 K=80 padded row stride (bf16 elems)  */
#define LD2 72          /* conv2/3 K=64 row stride                    */

/* ---- conv1: gather+concat + 80->64 --------------------------------------*/
__global__ void __launch_bounds__(256) conv1_mma(const float* __restrict__ xyz,
                                                 const float* __restrict__ feat,
                                                 const float* __restrict__ W, /* [64][67] */
                                                 int lgk)
{
    extern __shared__ char dyn[];
    __nv_bfloat16* Ah = (__nv_bfloat16*)dyn;          /* [128][LD1] */
    __nv_bfloat16* Al = Ah + 128*LD1;
    __nv_bfloat16* Bh = Al + 128*LD1;                 /* [64][LD1]  */
    __nv_bfloat16* Bl = Bh + 64*LD1;
    float* Cs = (float*)dyn;                          /* reuse: [128][64] */
    __shared__ float ps[4][64], pq[4][64];

    const int t = threadIdx.x, tile = blockIdx.x;
    const int wid = t >> 5;

    if (t < 128) {
        const int r = t;
        const int gr = tile*128 + r;
        const int q  = gr >> lgk;
        const int j  = gr & ((1 << lgk) - 1);
        const int n  = g_knn[q*KMAX + j];
        const int b  = q >> 10;
        const float* fp = feat + (size_t)(b*NN + n)*CF;
        unsigned* ah = (unsigned*)(Ah + r*LD1);
        unsigned* al = (unsigned*)(Al + r*LD1);
#pragma unroll
        for (int jj = 0; jj < 16; jj++) {
            float4 v = *(const float4*)(fp + jj*4);
            unsigned h0, l0, h1, l1;
            split2(v.x, v.y, h0, l0); split2(v.z, v.w, h1, l1);
            ah[jj*2]   = h0; ah[jj*2+1] = h1;
            al[jj*2]   = l0; al[jj*2+1] = l1;
        }
        const float* xp = xyz + (size_t)(b*NN + n)*3;
        float dx = xp[0]-g_newxyz[q*3+0], dy = xp[1]-g_newxyz[q*3+1], dz = xp[2]-g_newxyz[q*3+2];
        unsigned h0, l0, h1, l1;
        split2(dx, dy, h0, l0); split2(dz, 0.f, h1, l1);
        ah[32] = h0; ah[33] = h1; al[32] = l0; al[33] = l1;
#pragma unroll
        for (int z = 34; z < 40; z++) { ah[z] = 0u; al[z] = 0u; }
    } else if (t < 192) {
        const int n = t - 128;
        const float* w = W + n*CIN;
        unsigned* bh = (unsigned*)(Bh + n*LD1);
        unsigned* bl = (unsigned*)(Bl + n*LD1);
#pragma unroll
        for (int jj = 0; jj < 32; jj++) {
            unsigned h, l;
            split2(w[3 + jj*2], w[3 + jj*2 + 1], h, l);
            bh[jj] = h; bl[jj] = l;
        }
        unsigned h0, l0, h1, l1;
        split2(w[0], w[1], h0, l0); split2(w[2], 0.f, h1, l1);
        bh[32] = h0; bh[33] = h1; bl[32] = l0; bl[33] = l1;
#pragma unroll
        for (int z = 34; z < 40; z++) { bh[z] = 0u; bl[z] = 0u; }
    }
    __syncthreads();

    wmma::fragment<wmma::accumulator, 16, 16, 16, float> acc[4];
#pragma unroll
    for (int n = 0; n < 4; n++) wmma::fill_fragment(acc[n], 0.f);

    const __nv_bfloat16* AP[3] = {Ah, Al, Ah};
    const __nv_bfloat16* BP[3] = {Bh, Bh, Bl};
#pragma unroll
    for (int p = 0; p < 3; p++) {
#pragma unroll
        for (int ks = 0; ks < 5; ks++) {
            wmma::fragment<wmma::matrix_a, 16, 16, 16, __nv_bfloat16, wmma::row_major> af;
            wmma::load_matrix_sync(af, AP[p] + (wid*16)*LD1 + ks*16, LD1);
#pragma unroll
            for (int n = 0; n < 4; n++) {
                wmma::fragment<wmma::matrix_b, 16, 16, 16, __nv_bfloat16, wmma::col_major> bf;
                wmma::load_matrix_sync(bf, BP[p] + (n*16)*LD1 + ks*16, LD1);
                wmma::mma_sync(acc[n], af, bf, acc[n]);
            }
        }
    }
    __syncthreads();
#pragma unroll
    for (int n = 0; n < 4; n++)
        wmma::store_matrix_sync(Cs + (wid*16)*64 + n*16, acc[n], 64, wmma::mem_row_major);
    __syncthreads();

    const size_t base = (size_t)tile*128*64;
    for (int i = t*4; i < 128*64; i += 1024)
        *(float4*)(g_buf1 + base + i) = *(const float4*)(Cs + i);

    {
        const int c = t & 63, rq = t >> 6;
        float s = 0.f, q2 = 0.f;
#pragma unroll 8
        for (int r0 = 0; r0 < 32; r0++) {
            float v = Cs[(rq*32 + r0)*64 + c];
            s += v; q2 = fmaf(v, v, q2);
        }
        ps[rq][c] = s; pq[rq][c] = q2;
    }
    __syncthreads();
    if (t < 64) {
        atomicAdd(&g_sum[t], (double)(ps[0][t]+ps[1][t]+ps[2][t]+ps[3][t]));
        atomicAdd(&g_sq[t],  (double)(pq[0][t]+pq[1][t]+pq[2][t]+pq[3][t]));
    }
}

/* ---- conv2: BN+ReLU load + 64->64 ---------------------------------------*/
__global__ void __launch_bounds__(256) conv2_mma(const float* __restrict__ W /* [64][64] */)
{
    extern __shared__ char dyn[];
    __nv_bfloat16* Ah = (__nv_bfloat16*)dyn;          /* [128][LD2] */
    __nv_bfloat16* Al = Ah + 128*LD2;
    __nv_bfloat16* Bh = Al + 128*LD2;                 /* [64][LD2]  */
    __nv_bfloat16* Bl = Bh + 64*LD2;
    float* Cs = (float*)dyn;
    __shared__ float sc[64], sh[64], ps[4][64], pq[4][64];

    const int t = threadIdx.x, tile = blockIdx.x;
    const int wid = t >> 5;

    if (t < 64) { sc[t] = g_scl[t]; sh[t] = g_shf[t]; }
    __syncthreads();

    if (t < 128) {
        const int r = t;
        const float* ip = g_buf1 + ((size_t)tile*128 + r)*64;
        unsigned* ah = (unsigned*)(Ah + r*LD2);
        unsigned* al = (unsigned*)(Al + r*LD2);
#pragma unroll
        for (int jj = 0; jj < 16; jj++) {
            float4 v = *(const float4*)(ip + jj*4);
            int c0 = jj*4;
            float a = fmaxf(fmaf(v.x, sc[c0+0], sh[c0+0]), 0.f);
            float b = fmaxf(fmaf(v.y, sc[c0+1], sh[c0+1]), 0.f);
            float c = fmaxf(fmaf(v.z, sc[c0+2], sh[c0+2]), 0.f);
            float d = fmaxf(fmaf(v.w, sc[c0+3], sh[c0+3]), 0.f);
            unsigned h0, l0, h1, l1;
            split2(a, b, h0, l0); split2(c, d, h1, l1);
            ah[jj*2] = h0; ah[jj*2+1] = h1;
            al[jj*2] = l0; al[jj*2+1] = l1;
        }
    } else if (t < 192) {
        const int n = t - 128;
        const float* w = W + n*64;
        unsigned* bh = (unsigned*)(Bh + n*LD2);
        unsigned* bl = (unsigned*)(Bl + n*LD2);
#pragma unroll
        for (int jj = 0; jj < 16; jj++) {
            float4 v = *(const float4*)(w + jj*4);
            unsigned h0, l0, h1, l1;
            split2(v.x, v.y, h0, l0); split2(v.z, v.w, h1, l1);
            bh[jj*2] = h0; bh[jj*2+1] = h1;
            bl[jj*2] = l0; bl[jj*2+1] = l1;
        }
    }
    __syncthreads();

    wmma::fragment<wmma::accumulator, 16, 16, 16, float> acc[4];
#pragma unroll
    for (int n = 0; n < 4; n++) wmma::fill_fragment(acc[n], 0.f);

    const __nv_bfloat16* AP[3] = {Ah, Al, Ah};
    const __nv_bfloat16* BP[3] = {Bh, Bh, Bl};
#pragma unroll
    for (int p = 0; p < 3; p++) {
#pragma unroll
        for (int ks = 0; ks < 4; ks++) {
            wmma::fragment<wmma::matrix_a, 16, 16, 16, __nv_bfloat16, wmma::row_major> af;
            wmma::load_matrix_sync(af, AP[p] + (wid*16)*LD2 + ks*16, LD2);
#pragma unroll
            for (int n = 0; n < 4; n++) {
                wmma::fragment<wmma::matrix_b, 16, 16, 16, __nv_bfloat16, wmma::col_major> bf;
                wmma::load_matrix_sync(bf, BP[p] + (n*16)*LD2 + ks*16, LD2);
                wmma::mma_sync(acc[n], af, bf, acc[n]);
            }
        }
    }
    __syncthreads();
#pragma unroll
    for (int n = 0; n < 4; n++)
        wmma::store_matrix_sync(Cs + (wid*16)*64 + n*16, acc[n], 64, wmma::mem_row_major);
    __syncthreads();

    const size_t base = (size_t)tile*128*64;
    for (int i = t*4; i < 128*64; i += 1024)
        *(float4*)(g_buf2 + base + i) = *(const float4*)(Cs + i);

    {
        const int c = t & 63, rq = t >> 6;
        float s = 0.f, q2 = 0.f;
#pragma unroll 8
        for (int r0 = 0; r0 < 32; r0++) {
            float v = Cs[(rq*32 + r0)*64 + c];
            s += v; q2 = fmaf(v, v, q2);
        }
        ps[rq][c] = s; pq[rq][c] = q2;
    }
    __syncthreads();
    if (t < 64) {
        atomicAdd(&g_sum[t], (double)(ps[0][t]+ps[1][t]+ps[2][t]+ps[3][t]));
        atomicAdd(&g_sq[t],  (double)(pq[0][t]+pq[1][t]+pq[2][t]+pq[3][t]));
    }
}

/* ---- conv3: BN+ReLU load + 64->128 + per-query max/min ------------------ */
template<int K>
__global__ void __launch_bounds__(256) conv3_mma(const float* __restrict__ W /* [128][64] */)
{
    extern __shared__ char dyn[];
    __nv_bfloat16* Ah = (__nv_bfloat16*)dyn;          /* [128][LD2] */
    __nv_bfloat16* Al = Ah + 128*LD2;
    __nv_bfloat16* Bh = Al + 128*LD2;                 /* [128][LD2] */
    __nv_bfloat16* Bl = Bh + 128*LD2;
    float* Cs = (float*)dyn;                          /* reuse: [128][128] */
    __shared__ float sc[64], sh[64], ps[2][128], pq[2][128];

    const int t = threadIdx.x, tile = blockIdx.x;
    const int wid = t >> 5;

    if (t < 64) { sc[t] = g_scl[t]; sh[t] = g_shf[t]; }
    __syncthreads();

    if (t < 128) {
        const int r = t;
        const float* ip = g_buf2 + ((size_t)tile*128 + r)*64;
        unsigned* ah = (unsigned*)(Ah + r*LD2);
        unsigned* al = (unsigned*)(Al + r*LD2);
#pragma unroll
        for (int jj = 0; jj < 16; jj++) {
            float4 v = *(const float4*)(ip + jj*4);
            int c0 = jj*4;
            float a = fmaxf(fmaf(v.x, sc[c0+0], sh[c0+0]), 0.f);
            float b = fmaxf(fmaf(v.y, sc[c0+1], sh[c0+1]), 0.f);
            float c = fmaxf(fmaf(v.z, sc[c0+2], sh[c0+2]), 0.f);
            float d = fmaxf(fmaf(v.w, sc[c0+3], sh[c0+3]), 0.f);
            unsigned h0, l0, h1, l1;
            split2(a, b, h0, l0); split2(c, d, h1, l1);
            ah[jj*2] = h0; ah[jj*2+1] = h1;
            al[jj*2] = l0; al[jj*2+1] = l1;
        }
    } else {
        const int n = t - 128;                        /* one row per thread */
        const float* w = W + (size_t)n*64;
        unsigned* bh = (unsigned*)(Bh + n*LD2);
        unsigned* bl = (unsigned*)(Bl + n*LD2);
#pragma unroll
        for (int jj = 0; jj < 16; jj++) {
            float4 v = *(const float4*)(w + jj*4);
            unsigned h0, l0, h1, l1;
            split2(v.x, v.y, h0, l0); split2(v.z, v.w, h1, l1);
            bh[jj*2] = h0; bh[jj*2+1] = h1;
            bl[jj*2] = l0; bl[jj*2+1] = l1;
        }
    }
    __syncthreads();

    wmma::fragment<wmma::accumulator, 16, 16, 16, float> acc[8];
#pragma unroll
    for (int n = 0; n < 8; n++) wmma::fill_fragment(acc[n], 0.f);

    const __nv_bfloat16* AP[3] = {Ah, Al, Ah};
    const __nv_bfloat16* BP[3] = {Bh, Bh, Bl};
#pragma unroll
    for (int p = 0; p < 3; p++) {
#pragma unroll
        for (int ks = 0; ks < 4; ks++) {
            wmma::fragment<wmma::matrix_a, 16, 16, 16, __nv_bfloat16, wmma::row_major> af;
            wmma::load_matrix_sync(af, AP[p] + (wid*16)*LD2 + ks*16, LD2);
#pragma unroll
            for (int n = 0; n < 8; n++) {
                wmma::fragment<wmma::matrix_b, 16, 16, 16, __nv_bfloat16, wmma::col_major> bf;
                wmma::load_matrix_sync(bf, BP[p] + (n*16)*LD2 + ks*16, LD2);
                wmma::mma_sync(acc[n], af, bf, acc[n]);
            }
        }
    }
    __syncthreads();
#pragma unroll
    for (int n = 0; n < 8; n++)
        wmma::store_matrix_sync(Cs + (wid*16)*128 + n*16, acc[n], 128, wmma::mem_row_major);
    __syncthreads();

    /* stats: 2 row-halves x 128 cols */
    {
        const int c = t & 127, rh = t >> 7;
        float s = 0.f, q2 = 0.f;
#pragma unroll 8
        for (int r0 = 0; r0 < 64; r0++) {
            float v = Cs[(rh*64 + r0)*128 + c];
            s += v; q2 = fmaf(v, v, q2);
        }
        ps[rh][c] = s; pq[rh][c] = q2;
    }
    /* per-query max/min: query = K consecutive rows */
    {
        const int c = t & 127, g = t >> 7;
        const int nq_tile = 128 / K;
        for (int qi = g; qi < nq_tile; qi += 2) {
            float mx = -3.4e38f, mn = 3.4e38f;
#pragma unroll 8
            for (int r0 = 0; r0 < K; r0++) {
                float v = Cs[(qi*K + r0)*128 + c];
                mx = fmaxf(mx, v); mn = fminf(mn, v);
            }
            const int q = tile*nq_tile + qi;
            g_max[q*128 + c] = mx;
            g_min[q*128 + c] = mn;
        }
    }
    __syncthreads();
    if (t < 128) {
        atomicAdd(&g_sum[t], (double)(ps[0][t] + ps[1][t]));
        atomicAdd(&g_sq[t],  (double)(pq[0][t] + pq[1][t]));
    }
}

/* -------------- stats: sums -> (scale, shift); re-zero ------------------- */
__global__ void stats_kernel(const float* __restrict__ gamma,
                             const float* __restrict__ beta,
                             int C, double invn)
{
    int c = threadIdx.x;
    if (c < C) {
        double s = g_sum[c], q = g_sq[c];
        double mu = s * invn;
        double var = q * invn - mu * mu;
        float rstd = rsqrtf((float)var + 1e-5f);
        float scl = gamma[c] * rstd;
        g_scl[c] = scl;
        g_shf[c] = beta[c] - (float)mu * scl;
        g_sum[c] = 0.0;
        g_sq[c]  = 0.0;
    }
}

/* -------- finalize: BN(+sign-aware max/min) + ReLU -> out ---------------- */
__global__ void __launch_bounds__(128) finalize_kernel(float* __restrict__ out, int base)
{
    const int q = blockIdx.x;
    const int c = threadIdx.x;
    const float scl = g_scl[c], shf = g_shf[c];
    float sel = (scl >= 0.f) ? g_max[q*128 + c] : g_min[q*128 + c];
    out[(size_t)NQ*3 + (size_t)q*384 + base + c] = fmaxf(fmaf(sel, scl, shf), 0.f);
}

/* ------------------------------ driver ----------------------------------- */
extern "C" void kernel_launch(void* const* d_in, const int* in_sizes, int n_in,
                              void* d_out, int out_size)
{
    const float* xyz  = (const float*)d_in[0];
    const float* feat = (const float*)d_in[1];
    const float* w0   = (const float*)d_in[2];
    const float* w1   = (const float*)d_in[3];
    const float* w2   = (const float*)d_in[4];
    const float* g0   = (const float*)d_in[5];
    const float* g1   = (const float*)d_in[6];
    const float* g2   = (const float*)d_in[7];
    const float* b0   = (const float*)d_in[8];
    const float* b1   = (const float*)d_in[9];
    const float* b2   = (const float*)d_in[10];
    float* out = (float*)d_out;

    const int SM1 = (2*128*LD1 + 2*64*LD1) * 2;     /* 67584 */
    const int SM2 = (2*128*LD2 + 2*64*LD2) * 2;     /* 55296 */
    const int SM3 = (2*128*LD2 + 2*128*LD2) * 2;    /* 73728 */
    cudaFuncSetAttribute(conv1_mma, cudaFuncAttributeMaxDynamicSharedMemorySize, SM1);
    cudaFuncSetAttribute(conv2_mma, cudaFuncAttributeMaxDynamicSharedMemorySize, SM2);
    cudaFuncSetAttribute(conv3_mma<16>, cudaFuncAttributeMaxDynamicSharedMemorySize, SM3);
    cudaFuncSetAttribute(conv3_mma<32>, cudaFuncAttributeMaxDynamicSharedMemorySize, SM3);
    cudaFuncSetAttribute(conv3_mma<64>, cudaFuncAttributeMaxDynamicSharedMemorySize, SM3);

    init_kernel<<<1, 128>>>();
    fps_kernel<<<BB, 1024>>>(xyz, out);
    knn_kernel<<<NQ, 128>>>(xyz);

    const int KS[3]  = {16, 32, 64};
    const int LGK[3] = {4, 5, 6};
    for (int s = 0; s < 3; s++) {
        const int k = KS[s];
        const int R = NQ * k;
        const double invn = 1.0 / (double)R;

        conv1_mma<<<R/128, 256, SM1>>>(xyz, feat, w0 + (size_t)s*64*CIN, LGK[s]);
        stats_kernel<<<1, 128>>>(g0 + s*64, b0 + s*64, 64, invn);

        conv2_mma<<<R/128, 256, SM2>>>(w1 + (size_t)s*64*64);
        stats_kernel<<<1, 128>>>(g1 + s*64, b1 + s*64, 64, invn);

        if (k == 16)      conv3_mma<16><<<R/128, 256, SM3>>>(w2 + (size_t)s*128*64);
        else if (k == 32) conv3_mma<32><<<R/128, 256, SM3>>>(w2 + (size_t)s*128*64);
        else              conv3_mma<64><<<R/128, 256, SM3>>>(w2 + (size_t)s*128*64);
        stats_kernel<<<1, 128>>>(g2 + s*128, b2 + s*128, 128, invn);

        finalize_kernel<<<NQ, 128>>>(out, s*128);
    }
}

// round 9
// speedup vs baseline: 2.4604x; 1.2559x over previous
#include <cuda_runtime.h>
#include <cuda_bf16.h>
#include <mma.h>
#include <cstdint>

using namespace nvcuda;

#define BB 16
#define NN 4096
#define SS 1024
#define NQ (BB*SS)
#define KMAX 64
#define CIN 67
#define CF  64

/* ---------------- scratch (device globals; no allocation allowed) -------- */
__device__ int    g_knn[NQ*KMAX];
__device__ float  g_newxyz[NQ*3];
#define B1OFF0 0
#define B1OFF1 (16384u*16u*64u)
#define B1OFF2 (B1OFF1 + 16384u*32u*64u)
#define B1TOT  (B1OFF2 + 16384u*64u*64u)
__device__ float  g_buf1[B1TOT];
__device__ float  g_buf2[B1TOT];
__device__ float  g_max[(size_t)3*NQ*128];
__device__ float  g_min[(size_t)3*NQ*128];
__device__ double g_sum[3][128];
__device__ double g_sq[3][128];
__device__ float  g_scl[3][128];
__device__ float  g_shf[3][128];

/* split a,b (fp32) into packed bf16 hi-pair and lo-pair (a in low 16 bits) */
__device__ __forceinline__ void split2(float a, float b, unsigned &hi, unsigned &lo)
{
    __nv_bfloat16 ah = __float2bfloat16(a), bh = __float2bfloat16(b);
    float ar = a - __bfloat162float(ah), br = b - __bfloat162float(bh);
    __nv_bfloat16 al = __float2bfloat16(ar), bl = __float2bfloat16(br);
    hi = (unsigned)__bfloat16_as_ushort(ah) | ((unsigned)__bfloat16_as_ushort(bh) << 16);
    lo = (unsigned)__bfloat16_as_ushort(al) | ((unsigned)__bfloat16_as_ushort(bl) << 16);
}

/* --------------------------- init / noop ---------------------------------- */
__global__ void init_kernel()
{
    int t = threadIdx.x;
    if (t < 128) {
        g_sum[0][t] = 0.0; g_sq[0][t] = 0.0;
        g_sum[1][t] = 0.0; g_sq[1][t] = 0.0;
        g_sum[2][t] = 0.0; g_sq[2][t] = 0.0;
    }
}
__global__ void noop_kernel() {}

/* ------------------------------- FPS ------------------------------------ */
__global__ void __launch_bounds__(1024) fps_kernel(const float* __restrict__ xyz,
                                                   float* __restrict__ out_newxyz)
{
    const int b = blockIdx.x;
    const int t = threadIdx.x;
    const int lane = t & 31, wid = t >> 5;
    const float* X = xyz + (size_t)b*NN*3;

    float px[4], py[4], pz[4], dd[4];
#pragma unroll
    for (int j = 0; j < 4; j++) {
        int p = t + 1024*j;
        px[j] = X[p*3+0]; py[j] = X[p*3+1]; pz[j] = X[p*3+2];
        dd[j] = 1e10f;
    }
    __shared__ unsigned long long wb[32];
    int far = 0;

    for (int it = 0; it < SS; ++it) {
        float cx = X[far*3+0], cy = X[far*3+1], cz = X[far*3+2];
        if (t == 0) {
            int o = b*SS + it;
            out_newxyz[o*3+0] = cx; out_newxyz[o*3+1] = cy; out_newxyz[o*3+2] = cz;
            g_newxyz[o*3+0]  = cx; g_newxyz[o*3+1]  = cy; g_newxyz[o*3+2]  = cz;
        }
        unsigned long long best = 0ull;
#pragma unroll
        for (int j = 0; j < 4; j++) {
            float dx = px[j]-cx, dy = py[j]-cy, dz = pz[j]-cz;
            float d  = fmaf(dz, dz, fmaf(dy, dy, dx*dx));
            dd[j] = fminf(dd[j], d);
            int p = t + 1024*j;
            unsigned long long key =
                (((unsigned long long)__float_as_uint(dd[j])) << 32) | (unsigned)(NN-1-p);
            best = (key > best) ? key : best;
        }
#pragma unroll
        for (int o = 16; o; o >>= 1) {
            unsigned long long v = __shfl_xor_sync(0xffffffffu, best, o);
            if (v > best) best = v;
        }
        if (lane == 0) wb[wid] = best;
        __syncthreads();
        unsigned long long v = wb[lane];
#pragma unroll
        for (int o = 16; o; o >>= 1) {
            unsigned long long u = __shfl_xor_sync(0xffffffffu, v, o);
            if (u > v) v = u;
        }
        far = NN - 1 - (int)(v & 0xffffffffu);
        __syncthreads();
    }
}

/* ------------------- kNN: O(N) radix-select + bitonic -------------------- */
__device__ __forceinline__ unsigned mono_f32(float v)
{
    unsigned u = __float_as_uint(v);
    return (u & 0x80000000u) ? ~u : (u | 0x80000000u);
}

__global__ void __launch_bounds__(128) knn_kernel(const float* __restrict__ xyz)
{
    const int q = blockIdx.x;
    const int b = q >> 10;
    const int t = threadIdx.x;
    const int lane = t & 31;
    __shared__ unsigned hist[256];
    __shared__ unsigned long long arr[64];
    __shared__ unsigned long long s_K;
    __shared__ int s_bin, s_r, s_cnt, s_pos;
    const float* X = xyz + (size_t)b*NN*3;

    const float qx = g_newxyz[q*3+0], qy = g_newxyz[q*3+1], qz = g_newxyz[q*3+2];
    const float qq = qx*qx + qy*qy + qz*qz;

    unsigned mk[32];
#pragma unroll 8
    for (int i = 0; i < 32; i++) {
        int p = t + 128*i;
        float x = X[p*3+0], y = X[p*3+1], z = X[p*3+2];
        float pp  = x*x + y*y + z*z;
        float dot = qx*x + qy*y + qz*z;
        float d2  = qq + pp - 2.0f*dot;           /* same formula as reference */
        mk[i] = mono_f32(d2);
    }

    /* radix-descend to the exact 64th-smallest key (key = mono<<32 | idx) */
    unsigned long long prefix = 0ull, pmask = 0ull;
    int r = KMAX;
    for (int shift = 56; shift >= 0; shift -= 8) {
        hist[t] = 0u; hist[t+128] = 0u;
        __syncthreads();
#pragma unroll 8
        for (int i = 0; i < 32; i++) {
            unsigned long long k = ((unsigned long long)mk[i] << 32) | (unsigned)(t + 128*i);
            if ((k & pmask) == prefix)
                atomicAdd(&hist[(unsigned)(k >> shift) & 255u], 1u);
        }
        __syncthreads();
        if (t < 32) {
            unsigned part = 0;
#pragma unroll
            for (int i = 0; i < 8; i++) part += hist[t*8 + i];
            unsigned cum = part;
#pragma unroll
            for (int o = 1; o < 32; o <<= 1) {
                unsigned v = __shfl_up_sync(0xffffffffu, cum, o);
                if (lane >= o) cum += v;
            }
            unsigned cb = cum - part;
            bool has = (cb < (unsigned)r) && ((unsigned)r <= cum);
            unsigned mball = __ballot_sync(0xffffffffu, has);
            if (t == __ffs(mball) - 1) {
                int rr = r - (int)cb;
                int bb = t*8;
                for (;;) {
                    unsigned h = hist[bb];
                    if (rr <= (int)h) { s_cnt = (int)h; break; }
                    rr -= (int)h; bb++;
                }
                s_bin = bb; s_r = rr;
            }
        }
        __syncthreads();
        prefix |= ((unsigned long long)(unsigned)s_bin) << shift;
        pmask  |= (255ull << shift);
        r = s_r;
        int cnt = s_cnt;
        __syncthreads();
        if (cnt == 1) break;
    }

    /* the unique key matching prefix is K64 */
#pragma unroll 8
    for (int i = 0; i < 32; i++) {
        unsigned long long k = ((unsigned long long)mk[i] << 32) | (unsigned)(t + 128*i);
        if ((k & pmask) == prefix) s_K = k;
    }
    if (t == 0) s_pos = 0;
    __syncthreads();
    const unsigned long long K64 = s_K;

    /* partition: exactly 64 keys <= K64 (keys unique) */
#pragma unroll 8
    for (int i = 0; i < 32; i++) {
        unsigned long long k = ((unsigned long long)mk[i] << 32) | (unsigned)(t + 128*i);
        if (k <= K64) {
            int pos = atomicAdd(&s_pos, 1);
            arr[pos] = k;
        }
    }
    __syncthreads();

    /* bitonic sort 64 keys ascending */
    for (int k2 = 2; k2 <= 64; k2 <<= 1)
        for (int j = k2 >> 1; j > 0; j >>= 1) {
            if (t < 64) {
                int ixj = t ^ j;
                if (ixj > t) {
                    unsigned long long a = arr[t], c = arr[ixj];
                    bool up = ((t & k2) == 0);
                    if ((a > c) == up) { arr[t] = c; arr[ixj] = a; }
                }
            }
            __syncthreads();
        }

    if (t < 64) g_knn[q*KMAX + t] = (int)(arr[t] & 0xffffffffu);
}

/* ================== WMMA bf16 (hi/lo split) conv kernels ================= */
#define LD1 88
#define LD2 72

/* ---- conv1: gather+concat + 80->64 --------------------------------------*/
__global__ void __launch_bounds__(256) conv1_mma(const float* __restrict__ xyz,
                                                 const float* __restrict__ feat,
                                                 const float* __restrict__ W,
                                                 int lgk, int s, unsigned boff)
{
    extern __shared__ char dyn[];
    __nv_bfloat16* Ah = (__nv_bfloat16*)dyn;          /* [128][LD1] */
    __nv_bfloat16* Al = Ah + 128*LD1;
    __nv_bfloat16* Bh = Al + 128*LD1;                 /* [64][LD1]  */
    __nv_bfloat16* Bl = Bh + 64*LD1;
    float* Cs = (float*)dyn;                          /* reuse: [128][64] */
    __shared__ float ps[4][64], pq[4][64];

    const int t = threadIdx.x, tile = blockIdx.x;
    const int wid = t >> 5;

    {
        const int r = t >> 1, sub = t & 1;
        const int gr = tile*128 + r;
        const int q  = gr >> lgk;
        const int j  = gr & ((1 << lgk) - 1);
        const int n  = g_knn[q*KMAX + j];
        const int b  = q >> 10;
        const float* fp = feat + (size_t)(b*NN + n)*CF;
        unsigned* ah = (unsigned*)(Ah + r*LD1);
        unsigned* al = (unsigned*)(Al + r*LD1);
#pragma unroll
        for (int jj = sub*8; jj < sub*8 + 8; jj++) {
            float4 v = *(const float4*)(fp + jj*4);
            unsigned h0, l0, h1, l1;
            split2(v.x, v.y, h0, l0); split2(v.z, v.w, h1, l1);
            ah[jj*2]   = h0; ah[jj*2+1] = h1;
            al[jj*2]   = l0; al[jj*2+1] = l1;
        }
        if (sub) {
            const float* xp = xyz + (size_t)(b*NN + n)*3;
            float dx = xp[0]-g_newxyz[q*3+0], dy = xp[1]-g_newxyz[q*3+1], dz = xp[2]-g_newxyz[q*3+2];
            unsigned h0, l0, h1, l1;
            split2(dx, dy, h0, l0); split2(dz, 0.f, h1, l1);
            ah[32] = h0; ah[33] = h1; al[32] = l0; al[33] = l1;
#pragma unroll
            for (int z = 34; z < 40; z++) { ah[z] = 0u; al[z] = 0u; }
        }
    }
    if (t < 128) {
        const int n = t >> 1, sub = t & 1;
        const float* w = W + n*CIN;
        unsigned* bh = (unsigned*)(Bh + n*LD1);
        unsigned* bl = (unsigned*)(Bl + n*LD1);
#pragma unroll
        for (int jj = sub*16; jj < sub*16 + 16; jj++) {
            unsigned h, l;
            split2(w[3 + jj*2], w[3 + jj*2 + 1], h, l);
            bh[jj] = h; bl[jj] = l;
        }
        if (sub) {
            unsigned h0, l0, h1, l1;
            split2(w[0], w[1], h0, l0); split2(w[2], 0.f, h1, l1);
            bh[32] = h0; bh[33] = h1; bl[32] = l0; bl[33] = l1;
#pragma unroll
            for (int z = 34; z < 40; z++) { bh[z] = 0u; bl[z] = 0u; }
        }
    }
    __syncthreads();

    const int rowg = wid >> 1, colg = wid & 1;
    wmma::fragment<wmma::accumulator, 16, 16, 16, float> acc[2][2];
#pragma unroll
    for (int i = 0; i < 2; i++)
#pragma unroll
        for (int j = 0; j < 2; j++) wmma::fill_fragment(acc[i][j], 0.f);

    const __nv_bfloat16* AP[3] = {Ah, Al, Ah};
    const __nv_bfloat16* BP[3] = {Bh, Bh, Bl};
#pragma unroll
    for (int p = 0; p < 3; p++) {
#pragma unroll
        for (int ks = 0; ks < 5; ks++) {
            wmma::fragment<wmma::matrix_a, 16, 16, 16, __nv_bfloat16, wmma::row_major> af[2];
            wmma::fragment<wmma::matrix_b, 16, 16, 16, __nv_bfloat16, wmma::col_major> bf[2];
#pragma unroll
            for (int i = 0; i < 2; i++)
                wmma::load_matrix_sync(af[i], AP[p] + (rowg*32 + i*16)*LD1 + ks*16, LD1);
#pragma unroll
            for (int j = 0; j < 2; j++)
                wmma::load_matrix_sync(bf[j], BP[p] + (colg*32 + j*16)*LD1 + ks*16, LD1);
#pragma unroll
            for (int i = 0; i < 2; i++)
#pragma unroll
                for (int j = 0; j < 2; j++)
                    wmma::mma_sync(acc[i][j], af[i], bf[j], acc[i][j]);
        }
    }
    __syncthreads();
#pragma unroll
    for (int i = 0; i < 2; i++)
#pragma unroll
        for (int j = 0; j < 2; j++)
            wmma::store_matrix_sync(Cs + (rowg*32 + i*16)*64 + colg*32 + j*16,
                                    acc[i][j], 64, wmma::mem_row_major);
    __syncthreads();

    float* bufOut = g_buf1 + boff;
    const size_t base = (size_t)tile*128*64;
    for (int i = t*4; i < 128*64; i += 1024)
        *(float4*)(bufOut + base + i) = *(const float4*)(Cs + i);

    {
        const int c = t & 63, rq = t >> 6;
        float sv = 0.f, q2 = 0.f;
#pragma unroll 8
        for (int r0 = 0; r0 < 32; r0++) {
            float v = Cs[(rq*32 + r0)*64 + c];
            sv += v; q2 = fmaf(v, v, q2);
        }
        ps[rq][c] = sv; pq[rq][c] = q2;
    }
    __syncthreads();
    if (t < 64) {
        atomicAdd(&g_sum[s][t], (double)(ps[0][t]+ps[1][t]+ps[2][t]+ps[3][t]));
        atomicAdd(&g_sq[s][t],  (double)(pq[0][t]+pq[1][t]+pq[2][t]+pq[3][t]));
    }
}

/* ---- conv2: BN+ReLU load + 64->64 ---------------------------------------*/
__global__ void __launch_bounds__(256) conv2_mma(const float* __restrict__ W,
                                                 int s, unsigned boff)
{
    extern __shared__ char dyn[];
    __nv_bfloat16* Ah = (__nv_bfloat16*)dyn;
    __nv_bfloat16* Al = Ah + 128*LD2;
    __nv_bfloat16* Bh = Al + 128*LD2;
    __nv_bfloat16* Bl = Bh + 64*LD2;
    float* Cs = (float*)dyn;
    __shared__ float sc[64], sh[64], ps[4][64], pq[4][64];

    const int t = threadIdx.x, tile = blockIdx.x;
    const int wid = t >> 5;

    if (t < 64) { sc[t] = g_scl[s][t]; sh[t] = g_shf[s][t]; }
    __syncthreads();

    {
        const int r = t >> 1, sub = t & 1;
        const float* ip = g_buf1 + boff + ((size_t)tile*128 + r)*64;
        unsigned* ah = (unsigned*)(Ah + r*LD2);
        unsigned* al = (unsigned*)(Al + r*LD2);
#pragma unroll
        for (int jj = sub*8; jj < sub*8 + 8; jj++) {
            float4 v = *(const float4*)(ip + jj*4);
            int c0 = jj*4;
            float a = fmaxf(fmaf(v.x, sc[c0+0], sh[c0+0]), 0.f);
            float b = fmaxf(fmaf(v.y, sc[c0+1], sh[c0+1]), 0.f);
            float c = fmaxf(fmaf(v.z, sc[c0+2], sh[c0+2]), 0.f);
            float d = fmaxf(fmaf(v.w, sc[c0+3], sh[c0+3]), 0.f);
            unsigned h0, l0, h1, l1;
            split2(a, b, h0, l0); split2(c, d, h1, l1);
            ah[jj*2] = h0; ah[jj*2+1] = h1;
            al[jj*2] = l0; al[jj*2+1] = l1;
        }
    }
    if (t < 128) {
        const int n = t >> 1, sub = t & 1;
        const float* w = W + n*64;
        unsigned* bh = (unsigned*)(Bh + n*LD2);
        unsigned* bl = (unsigned*)(Bl + n*LD2);
#pragma unroll
        for (int jj = sub*8; jj < sub*8 + 8; jj++) {
            float4 v = *(const float4*)(w + jj*4);
            unsigned h0, l0, h1, l1;
            split2(v.x, v.y, h0, l0); split2(v.z, v.w, h1, l1);
            bh[jj*2] = h0; bh[jj*2+1] = h1;
            bl[jj*2] = l0; bl[jj*2+1] = l1;
        }
    }
    __syncthreads();

    const int rowg = wid >> 1, colg = wid & 1;
    wmma::fragment<wmma::accumulator, 16, 16, 16, float> acc[2][2];
#pragma unroll
    for (int i = 0; i < 2; i++)
#pragma unroll
        for (int j = 0; j < 2; j++) wmma::fill_fragment(acc[i][j], 0.f);

    const __nv_bfloat16* AP[3] = {Ah, Al, Ah};
    const __nv_bfloat16* BP[3] = {Bh, Bh, Bl};
#pragma unroll
    for (int p = 0; p < 3; p++) {
#pragma unroll
        for (int ks = 0; ks < 4; ks++) {
            wmma::fragment<wmma::matrix_a, 16, 16, 16, __nv_bfloat16, wmma::row_major> af[2];
            wmma::fragment<wmma::matrix_b, 16, 16, 16, __nv_bfloat16, wmma::col_major> bf[2];
#pragma unroll
            for (int i = 0; i < 2; i++)
                wmma::load_matrix_sync(af[i], AP[p] + (rowg*32 + i*16)*LD2 + ks*16, LD2);
#pragma unroll
            for (int j = 0; j < 2; j++)
                wmma::load_matrix_sync(bf[j], BP[p] + (colg*32 + j*16)*LD2 + ks*16, LD2);
#pragma unroll
            for (int i = 0; i < 2; i++)
#pragma unroll
                for (int j = 0; j < 2; j++)
                    wmma::mma_sync(acc[i][j], af[i], bf[j], acc[i][j]);
        }
    }
    __syncthreads();
#pragma unroll
    for (int i = 0; i < 2; i++)
#pragma unroll
        for (int j = 0; j < 2; j++)
            wmma::store_matrix_sync(Cs + (rowg*32 + i*16)*64 + colg*32 + j*16,
                                    acc[i][j], 64, wmma::mem_row_major);
    __syncthreads();

    float* bufOut = g_buf2 + boff;
    const size_t base = (size_t)tile*128*64;
    for (int i = t*4; i < 128*64; i += 1024)
        *(float4*)(bufOut + base + i) = *(const float4*)(Cs + i);

    {
        const int c = t & 63, rq = t >> 6;
        float sv = 0.f, q2 = 0.f;
#pragma unroll 8
        for (int r0 = 0; r0 < 32; r0++) {
            float v = Cs[(rq*32 + r0)*64 + c];
            sv += v; q2 = fmaf(v, v, q2);
        }
        ps[rq][c] = sv; pq[rq][c] = q2;
    }
    __syncthreads();
    if (t < 64) {
        atomicAdd(&g_sum[s][t], (double)(ps[0][t]+ps[1][t]+ps[2][t]+ps[3][t]));
        atomicAdd(&g_sq[s][t],  (double)(pq[0][t]+pq[1][t]+pq[2][t]+pq[3][t]));
    }
}

/* ---- conv3: BN+ReLU load + 64->128 + per-query max/min ------------------ */
template<int K>
__global__ void __launch_bounds__(256) conv3_mma(const float* __restrict__ W,
                                                 int s, unsigned boff)
{
    extern __shared__ char dyn[];
    __nv_bfloat16* Ah = (__nv_bfloat16*)dyn;
    __nv_bfloat16* Al = Ah + 128*LD2;
    __nv_bfloat16* Bh = Al + 128*LD2;
    __nv_bfloat16* Bl = Bh + 128*LD2;
    float* Cs = (float*)dyn;                          /* [128][128] */
    __shared__ float sc[64], sh[64], ps[2][128], pq[2][128];

    const int t = threadIdx.x, tile = blockIdx.x;
    const int wid = t >> 5;

    if (t < 64) { sc[t] = g_scl[s][t]; sh[t] = g_shf[s][t]; }
    __syncthreads();

    {
        const int r = t >> 1, sub = t & 1;
        const float* ip = g_buf2 + boff + ((size_t)tile*128 + r)*64;
        unsigned* ah = (unsigned*)(Ah + r*LD2);
        unsigned* al = (unsigned*)(Al + r*LD2);
#pragma unroll
        for (int jj = sub*8; jj < sub*8 + 8; jj++) {
            float4 v = *(const float4*)(ip + jj*4);
            int c0 = jj*4;
            float a = fmaxf(fmaf(v.x, sc[c0+0], sh[c0+0]), 0.f);
            float b = fmaxf(fmaf(v.y, sc[c0+1], sh[c0+1]), 0.f);
            float c = fmaxf(fmaf(v.z, sc[c0+2], sh[c0+2]), 0.f);
            float d = fmaxf(fmaf(v.w, sc[c0+3], sh[c0+3]), 0.f);
            unsigned h0, l0, h1, l1;
            split2(a, b, h0, l0); split2(c, d, h1, l1);
            ah[jj*2] = h0; ah[jj*2+1] = h1;
            al[jj*2] = l0; al[jj*2+1] = l1;
        }
    }
    {
        const int n = t >> 1, sub = t & 1;
        const float* w = W + (size_t)n*64;
        unsigned* bh = (unsigned*)(Bh + n*LD2);
        unsigned* bl = (unsigned*)(Bl + n*LD2);
#pragma unroll
        for (int jj = sub*8; jj < sub*8 + 8; jj++) {
            float4 v = *(const float4*)(w + jj*4);
            unsigned h0, l0, h1, l1;
            split2(v.x, v.y, h0, l0); split2(v.z, v.w, h1, l1);
            bh[jj*2] = h0; bh[jj*2+1] = h1;
            bl[jj*2] = l0; bl[jj*2+1] = l1;
        }
    }
    __syncthreads();

    const int rowg = wid >> 1, colg = wid & 1;
    wmma::fragment<wmma::accumulator, 16, 16, 16, float> acc[2][4];
#pragma unroll
    for (int i = 0; i < 2; i++)
#pragma unroll
        for (int j = 0; j < 4; j++) wmma::fill_fragment(acc[i][j], 0.f);

    const __nv_bfloat16* AP[3] = {Ah, Al, Ah};
    const __nv_bfloat16* BP[3] = {Bh, Bh, Bl};
#pragma unroll
    for (int p = 0; p < 3; p++) {
#pragma unroll
        for (int ks = 0; ks < 4; ks++) {
            wmma::fragment<wmma::matrix_a, 16, 16, 16, __nv_bfloat16, wmma::row_major> af[2];
#pragma unroll
            for (int i = 0; i < 2; i++)
                wmma::load_matrix_sync(af[i], AP[p] + (rowg*32 + i*16)*LD2 + ks*16, LD2);
#pragma unroll
            for (int j = 0; j < 4; j++) {
                wmma::fragment<wmma::matrix_b, 16, 16, 16, __nv_bfloat16, wmma::col_major> bf;
                wmma::load_matrix_sync(bf, BP[p] + (colg*64 + j*16)*LD2 + ks*16, LD2);
#pragma unroll
                for (int i = 0; i < 2; i++)
                    wmma::mma_sync(acc[i][j], af[i], bf, acc[i][j]);
            }
        }
    }
    __syncthreads();
#pragma unroll
    for (int i = 0; i < 2; i++)
#pragma unroll
        for (int j = 0; j < 4; j++)
            wmma::store_matrix_sync(Cs + (rowg*32 + i*16)*128 + colg*64 + j*16,
                                    acc[i][j], 128, wmma::mem_row_major);
    __syncthreads();

    {
        const int c = t & 127, rh = t >> 7;
        float sv = 0.f, q2 = 0.f;
#pragma unroll 8
        for (int r0 = 0; r0 < 64; r0++) {
            float v = Cs[(rh*64 + r0)*128 + c];
            sv += v; q2 = fmaf(v, v, q2);
        }
        ps[rh][c] = sv; pq[rh][c] = q2;
    }
    {
        const int c = t & 127, g = t >> 7;
        const int nq_tile = 128 / K;
        float* gmax = g_max + (size_t)s*NQ*128;
        float* gmin = g_min + (size_t)s*NQ*128;
        for (int qi = g; qi < nq_tile; qi += 2) {
            float mx = -3.4e38f, mn = 3.4e38f;
#pragma unroll 8
            for (int r0 = 0; r0 < K; r0++) {
                float v = Cs[(qi*K + r0)*128 + c];
                mx = fmaxf(mx, v); mn = fminf(mn, v);
            }
            const int q = tile*nq_tile + qi;
            gmax[q*128 + c] = mx;
            gmin[q*128 + c] = mn;
        }
    }
    __syncthreads();
    if (t < 128) {
        atomicAdd(&g_sum[s][t], (double)(ps[0][t] + ps[1][t]));
        atomicAdd(&g_sq[s][t],  (double)(pq[0][t] + pq[1][t]));
    }
}

/* -------------- stats: sums -> (scale, shift); re-zero ------------------- */
__global__ void stats_kernel(const float* __restrict__ gamma,
                             const float* __restrict__ beta,
                             int C, double invn, int s)
{
    int c = threadIdx.x;
    if (c < C) {
        double sv = g_sum[s][c], q = g_sq[s][c];
        double mu = sv * invn;
        double var = q * invn - mu * mu;
        float rstd = rsqrtf((float)var + 1e-5f);
        float scl = gamma[c] * rstd;
        g_scl[s][c] = scl;
        g_shf[s][c] = beta[c] - (float)mu * scl;
        g_sum[s][c] = 0.0;
        g_sq[s][c]  = 0.0;
    }
}

/* -------- finalize: BN(+sign-aware max/min) + ReLU -> out ---------------- */
__global__ void __launch_bounds__(128) finalize_kernel(float* __restrict__ out, int s)
{
    const int q = blockIdx.x;
    const int c = threadIdx.x;
    const float scl = g_scl[s][c], shf = g_shf[s][c];
    const float* gmax = g_max + (size_t)s*NQ*128;
    const float* gmin = g_min + (size_t)s*NQ*128;
    float sel = (scl >= 0.f) ? gmax[q*128 + c] : gmin[q*128 + c];
    out[(size_t)NQ*3 + (size_t)q*384 + s*128 + c] = fmaxf(fmaf(sel, scl, shf), 0.f);
}

/* ------------------------------ driver ----------------------------------- */
extern "C" void kernel_launch(void* const* d_in, const int* in_sizes, int n_in,
                              void* d_out, int out_size)
{
    const float* xyz  = (const float*)d_in[0];
    const float* feat = (const float*)d_in[1];
    const float* w0   = (const float*)d_in[2];
    const float* w1   = (const float*)d_in[3];
    const float* w2   = (const float*)d_in[4];
    const float* g0   = (const float*)d_in[5];
    const float* g1   = (const float*)d_in[6];
    const float* g2   = (const float*)d_in[7];
    const float* b0   = (const float*)d_in[8];
    const float* b1   = (const float*)d_in[9];
    const float* b2   = (const float*)d_in[10];
    float* out = (float*)d_out;

    const int SM1 = (2*128*LD1 + 2*64*LD1) * 2;
    const int SM2 = (2*128*LD2 + 2*64*LD2) * 2;
    const int SM3 = (2*128*LD2 + 2*128*LD2) * 2;
    cudaFuncSetAttribute(conv1_mma, cudaFuncAttributeMaxDynamicSharedMemorySize, SM1);
    cudaFuncSetAttribute(conv2_mma, cudaFuncAttributeMaxDynamicSharedMemorySize, SM2);
    cudaFuncSetAttribute(conv3_mma<16>, cudaFuncAttributeMaxDynamicSharedMemorySize, SM3);
    cudaFuncSetAttribute(conv3_mma<32>, cudaFuncAttributeMaxDynamicSharedMemorySize, SM3);
    cudaFuncSetAttribute(conv3_mma<64>, cudaFuncAttributeMaxDynamicSharedMemorySize, SM3);

    init_kernel<<<1, 128>>>();
    fps_kernel<<<BB, 1024>>>(xyz, out);
    noop_kernel<<<1, 32>>>();
    knn_kernel<<<NQ, 128>>>(xyz);

    const int      KS[3]  = {16, 32, 64};
    const int      LGK[3] = {4, 5, 6};
    const unsigned OFF[3] = {B1OFF0, B1OFF1, B1OFF2};

    for (int s = 0; s < 3; s++) {
        const int k = KS[s];
        const int R = NQ * k;
        const double invn = 1.0 / (double)R;

        conv1_mma<<<R/128, 256, SM1>>>(xyz, feat, w0 + (size_t)s*64*CIN, LGK[s], s, OFF[s]);
        stats_kernel<<<1, 128>>>(g0 + s*64, b0 + s*64, 64, invn, s);

        conv2_mma<<<R/128, 256, SM2>>>(w1 + (size_t)s*64*64, s, OFF[s]);
        stats_kernel<<<1, 128>>>(g1 + s*64, b1 + s*64, 64, invn, s);

        if (k == 16)      conv3_mma<16><<<R/128, 256, SM3>>>(w2 + (size_t)s*128*64, s, OFF[s]);
        else if (k == 32) conv3_mma<32><<<R/128, 256, SM3>>>(w2 + (size_t)s*128*64, s, OFF[s]);
        else              conv3_mma<64><<<R/128, 256, SM3>>>(w2 + (size_t)s*128*64, s, OFF[s]);
        stats_kernel<<<1, 128>>>(g2 + s*128, b2 + s*128, 128, invn, s);

        finalize_kernel<<<NQ, 128>>>(out, s);
    }
}